// round 5
// baseline (speedup 1.0000x reference)
#include <cuda_runtime.h>
#include <math.h>

#define NN 50000
#define EE 800000
#define ET (EE + NN)
#define GG 64
#define F_IN 128
#define H1DIM 256   // HEADS * HID
#define H2DIM 32
#define NEG_SLOPE 0.2f

// ---------------- scratch ----------------
__device__ __align__(16) float g_h1[NN * H1DIM];
__device__ __align__(16) float g_out1[NN * H1DIM];
__device__ __align__(16) float g_as1[NN * 4];
__device__ __align__(16) float g_ad1[NN * 4];
__device__ __align__(16) float g_ex1[ET * 4];
__device__ __align__(16) float g_h2[NN * H2DIM];
__device__ float g_as2[NN];
__device__ float g_ad2[NN];
__device__ float g_ex2[ET];
__device__ float g_pool[GG * H2DIM];
__device__ float g_cnt[GG];
__device__ int g_deg[NN];          // zeroed by scatter for next replay
__device__ int g_cur[NN];
__device__ int g_off[NN + 1];
__device__ int g_csr_src[ET];
__device__ int g_csr_dst[ET];
__device__ __align__(16) float g_wsd1[F_IN * 8];   // [f][s0..s3,d0..d3]

// ---------------- helpers ----------------
__device__ __forceinline__ float leaky(float e) {
    return (e >= 0.f) ? e : NEG_SLOPE * e;
}
__device__ __forceinline__ unsigned long long pack2(float a, float b) {
    unsigned long long r;
    asm("mov.b64 %0, {%1, %2};" : "=l"(r) : "f"(a), "f"(b));
    return r;
}
__device__ __forceinline__ void unpack2(unsigned long long v, float& a, float& b) {
    asm("mov.b64 {%0, %1}, %2;" : "=f"(a), "=f"(b) : "l"(v));
}
__device__ __forceinline__ void fma2(unsigned long long& acc, unsigned long long a, unsigned long long b) {
    asm("fma.rn.f32x2 %0, %1, %2, %0;" : "+l"(acc) : "l"(a), "l"(b));
}

// ---------------- prep: folded attention vectors + zero pool ----------------
__global__ void prep_kernel(const float* __restrict__ W1,
                            const float* __restrict__ a1s, const float* __restrict__ a1d) {
    int tid = threadIdx.x;  // 1024
    {
        int f = tid >> 3, o = tid & 7;
        int h = o & 3, sd = o >> 2;
        const float* a = sd ? a1d : a1s;
        float s = 0.f;
#pragma unroll 8
        for (int d = 0; d < 64; d++) s += W1[f * H1DIM + h * 64 + d] * a[h * 64 + d];
        g_wsd1[f * 8 + o] = s;
    }
    for (int j = tid; j < GG * H2DIM; j += 1024) g_pool[j] = 0.f;
    if (tid < GG) g_cnt[tid] = 0.f;
}

// ---------------- CSR build ----------------
__global__ void hist_kernel(const int* __restrict__ adj) {
    int e = blockIdx.x * blockDim.x + threadIdx.x;
    if (e >= ET) return;
    int dst = (e < EE) ? adj[EE + e] : e - EE;
    atomicAdd(&g_deg[dst], 1);
}

__global__ void scan_kernel() {
    __shared__ int part[1024];
    int tid = threadIdx.x;
    const int CH = (NN + 1023) / 1024;
    int start = tid * CH;
    int end = min(start + CH, NN);
    int s = 0;
    for (int i = start; i < end; i++) s += g_deg[i];
    part[tid] = s;
    __syncthreads();
    for (int off = 1; off < 1024; off <<= 1) {
        int v = (tid >= off) ? part[tid - off] : 0;
        __syncthreads();
        part[tid] += v;
        __syncthreads();
    }
    int base = (tid == 0) ? 0 : part[tid - 1];
    for (int i = start; i < end; i++) {
        g_off[i] = base;
        g_cur[i] = base;
        base += g_deg[i];
    }
    if (tid == 1023) g_off[NN] = part[1023];
}

__global__ void scatter_kernel(const int* __restrict__ adj) {
    int gt = blockIdx.x * blockDim.x + threadIdx.x;
    int stride = gridDim.x * blockDim.x;
    for (int j = gt; j < NN; j += stride) g_deg[j] = 0;   // reset for next replay
    if (gt >= ET) return;
    int src, dst;
    if (gt < EE) { src = adj[gt]; dst = adj[EE + gt]; }
    else         { src = dst = gt - EE; }
    int p = atomicAdd(&g_cur[dst], 1);
    g_csr_src[p] = src;
    g_csr_dst[p] = dst;
}

// ---------------- GEMM1: h1 = x @ W1 (50000x128 @ 128x256), f32x2, 16 rows/blk ----------------
__global__ void gemm1_kernel(const float* __restrict__ x, const float* __restrict__ W1) {
    __shared__ float xs[16][F_IN];
    int row0 = blockIdx.x * 16;
    int tid = threadIdx.x;
    const float4* xsrc = (const float4*)(x + row0 * F_IN);
    float4* xdst = (float4*)&xs[0][0];
#pragma unroll
    for (int i = tid; i < 16 * F_IN / 4; i += 256) xdst[i] = xsrc[i];
    __syncthreads();
    int col = tid;
    unsigned long long acc[16];
#pragma unroll
    for (int r = 0; r < 16; r++) acc[r] = 0ull;
#pragma unroll 4
    for (int k = 0; k < F_IN; k += 2) {
        float w0 = W1[k * H1DIM + col];
        float w1 = W1[(k + 1) * H1DIM + col];
        unsigned long long wp = pack2(w0, w1);
#pragma unroll
        for (int r = 0; r < 16; r++) {
            unsigned long long xv = *(const unsigned long long*)&xs[r][k];
            fma2(acc[r], xv, wp);
        }
    }
#pragma unroll
    for (int r = 0; r < 16; r++) {
        float lo, hi; unpack2(acc[r], lo, hi);
        g_h1[(row0 + r) * H1DIM + col] = lo + hi;
    }
}

// ---------------- alpha1: as1/ad1 = x @ wsd1 (warp per node) ----------------
__global__ void alpha1_kernel(const float* __restrict__ x) {
    int gt = blockIdx.x * blockDim.x + threadIdx.x;
    int n = gt >> 5, lane = gt & 31;
    if (n >= NN) return;
    float4 xv = ((const float4*)x)[n * 32 + lane];
    float a0 = 0, a1 = 0, a2 = 0, a3 = 0, b0 = 0, b1 = 0, b2 = 0, b3 = 0;
    float xj[4] = {xv.x, xv.y, xv.z, xv.w};
#pragma unroll
    for (int j = 0; j < 4; j++) {
        int f = lane * 4 + j;
        float4 wa = *(const float4*)&g_wsd1[f * 8];
        float4 wb = *(const float4*)&g_wsd1[f * 8 + 4];
        a0 = fmaf(xj[j], wa.x, a0); a1 = fmaf(xj[j], wa.y, a1);
        a2 = fmaf(xj[j], wa.z, a2); a3 = fmaf(xj[j], wa.w, a3);
        b0 = fmaf(xj[j], wb.x, b0); b1 = fmaf(xj[j], wb.y, b1);
        b2 = fmaf(xj[j], wb.z, b2); b3 = fmaf(xj[j], wb.w, b3);
    }
#pragma unroll
    for (int off = 16; off; off >>= 1) {
        a0 += __shfl_xor_sync(0xffffffffu, a0, off);
        a1 += __shfl_xor_sync(0xffffffffu, a1, off);
        a2 += __shfl_xor_sync(0xffffffffu, a2, off);
        a3 += __shfl_xor_sync(0xffffffffu, a3, off);
        b0 += __shfl_xor_sync(0xffffffffu, b0, off);
        b1 += __shfl_xor_sync(0xffffffffu, b1, off);
        b2 += __shfl_xor_sync(0xffffffffu, b2, off);
        b3 += __shfl_xor_sync(0xffffffffu, b3, off);
    }
    if (lane == 0) {
        *(float4*)&g_as1[n * 4] = make_float4(a0, a1, a2, a3);
        *(float4*)&g_ad1[n * 4] = make_float4(b0, b1, b2, b3);
    }
}

// ---------------- edge exp (layer1), CSR order ----------------
__global__ void edge1_exp_kernel() {
    int p = blockIdx.x * blockDim.x + threadIdx.x;
    if (p >= ET) return;
    int src = g_csr_src[p], dst = g_csr_dst[p];
    float4 as = *(const float4*)&g_as1[src * 4];
    float4 ad = *(const float4*)&g_ad1[dst * 4];
    float4 ex;
    ex.x = expf(leaky(as.x + ad.x));
    ex.y = expf(leaky(as.y + ad.y));
    ex.z = expf(leaky(as.z + ad.z));
    ex.w = expf(leaky(as.w + ad.w));
    *(float4*)&g_ex1[p * 4] = ex;
}

// ---------------- agg1: out1 = relu((sum ex*h1[src]) / (sum ex) + b1) ----------------
__global__ void agg1_kernel(const float* __restrict__ b1) {
    int gt = blockIdx.x * blockDim.x + threadIdx.x;
    int n = gt >> 6;
    if (n >= NN) return;
    int c = gt & 63, head = c >> 4;
    int beg = g_off[n], end = g_off[n + 1];
    float4 acc = make_float4(0.f, 0.f, 0.f, 0.f);
    float den = 0.f;
    for (int i = beg; i < end; i++) {
        int s0 = g_csr_src[i];
        float e0 = g_ex1[i * 4 + head];
        float4 v0 = *(const float4*)&g_h1[s0 * H1DIM + c * 4];
        den += e0;
        acc.x = fmaf(e0, v0.x, acc.x);
        acc.y = fmaf(e0, v0.y, acc.y);
        acc.z = fmaf(e0, v0.z, acc.z);
        acc.w = fmaf(e0, v0.w, acc.w);
    }
    float inv = 1.0f / den;
    float4 b = ((const float4*)b1)[c];
    float4 o;
    o.x = fmaxf(fmaf(acc.x, inv, b.x), 0.f);
    o.y = fmaxf(fmaf(acc.y, inv, b.y), 0.f);
    o.z = fmaxf(fmaf(acc.z, inv, b.z), 0.f);
    o.w = fmaxf(fmaf(acc.w, inv, b.w), 0.f);
    *(float4*)&g_out1[n * H1DIM + c * 4] = o;
}

// ---------------- GEMM2 + alpha2: h2 = out1 @ W2 (50000x256 @ 256x32) ----------------
// 8 rows/block, W2 direct from global (L1-resident), fused alpha2 epilogue
__global__ void gemm2_kernel(const float* __restrict__ W2,
                             const float* __restrict__ a2s,
                             const float* __restrict__ a2d) {
    __shared__ float xs[8][H1DIM];
    int row0 = blockIdx.x * 8;
    int tid = threadIdx.x;
    const float4* xsrc = (const float4*)&g_out1[row0 * H1DIM];
    float4* xdst = (float4*)&xs[0][0];
#pragma unroll
    for (int i = tid; i < 8 * H1DIM / 4; i += 256) xdst[i] = xsrc[i];
    __syncthreads();
    int r = tid >> 5, c = tid & 31;
    unsigned long long acc = 0ull;
#pragma unroll 8
    for (int k = 0; k < H1DIM; k += 2) {
        float w0 = W2[k * H2DIM + c];
        float w1 = W2[(k + 1) * H2DIM + c];
        unsigned long long wp = pack2(w0, w1);
        unsigned long long xv = *(const unsigned long long*)&xs[r][k];
        fma2(acc, xv, wp);
    }
    float lo, hi; unpack2(acc, lo, hi);
    float hval = lo + hi;
    int row = row0 + r;
    g_h2[row * H2DIM + c] = hval;
    // fused alpha2 (warp = one row, lanes = 32 cols)
    float ps = hval * a2s[c];
    float pd = hval * a2d[c];
#pragma unroll
    for (int off = 16; off; off >>= 1) {
        ps += __shfl_xor_sync(0xffffffffu, ps, off);
        pd += __shfl_xor_sync(0xffffffffu, pd, off);
    }
    if (c == 0) { g_as2[row] = ps; g_ad2[row] = pd; }
}

// ---------------- edge exp (layer2) ----------------
__global__ void edge2_exp_kernel() {
    int p = blockIdx.x * blockDim.x + threadIdx.x;
    if (p >= ET) return;
    int src = g_csr_src[p], dst = g_csr_dst[p];
    g_ex2[p] = expf(leaky(g_as2[src] + g_ad2[dst]));
}

// ---------------- agg2 + bias + log_softmax + pool (warp per node) ----------------
__global__ void agg2_lsm_kernel(const float* __restrict__ b2, const int* __restrict__ batch) {
    int gt = blockIdx.x * blockDim.x + threadIdx.x;
    int n = gt >> 5;
    if (n >= NN) return;
    int lane = gt & 31;
    int beg = g_off[n], end = g_off[n + 1];
    float acc = 0.f, den = 0.f;
    for (int i = beg; i < end; i++) {
        int s0 = g_csr_src[i];
        float a0 = g_ex2[i];
        den += a0;
        acc = fmaf(a0, g_h2[s0 * H2DIM + lane], acc);
    }
    float v = acc / den + b2[lane];
    float mx = v;
#pragma unroll
    for (int off = 16; off; off >>= 1) mx = fmaxf(mx, __shfl_xor_sync(0xffffffffu, mx, off));
    float ex = expf(v - mx);
    float s = ex;
#pragma unroll
    for (int off = 16; off; off >>= 1) s += __shfl_xor_sync(0xffffffffu, s, off);
    float lsm = v - mx - logf(s);
    int b = batch[n];
    atomicAdd(&g_pool[b * H2DIM + lane], lsm);
    if (lane == 0) atomicAdd(&g_cnt[b], 1.0f);
}

// ---------------- final ----------------
__global__ void final_kernel(const float* __restrict__ lin_W, const float* __restrict__ lin_b,
                             float* __restrict__ out) {
    int g = threadIdx.x;
    if (g >= GG) return;
    float inv = 1.0f / fmaxf(g_cnt[g], 1.0f);
    float acc = lin_b[0];
#pragma unroll
    for (int j = 0; j < H2DIM; j++) acc += g_pool[g * H2DIM + j] * inv * lin_W[j];
    out[g] = acc;
}

// ---------------- launcher ----------------
extern "C" void kernel_launch(void* const* d_in, const int* in_sizes, int n_in,
                              void* d_out, int out_size) {
    const float* x      = (const float*)d_in[0];
    const int*   adj    = (const int*)d_in[1];
    const int*   batch  = (const int*)d_in[2];
    const float* W1     = (const float*)d_in[3];
    const float* a1_src = (const float*)d_in[4];
    const float* a1_dst = (const float*)d_in[5];
    const float* b1     = (const float*)d_in[6];
    const float* W2     = (const float*)d_in[7];
    const float* a2_src = (const float*)d_in[8];
    const float* a2_dst = (const float*)d_in[9];
    const float* b2     = (const float*)d_in[10];
    const float* lin_W  = (const float*)d_in[11];
    const float* lin_b  = (const float*)d_in[12];
    float* out = (float*)d_out;

    const int TB = 256;
    int eb = (ET + TB - 1) / TB;

    prep_kernel<<<1, 1024>>>(W1, a1_src, a1_dst);
    hist_kernel<<<eb, TB>>>(adj);
    scan_kernel<<<1, 1024>>>();
    scatter_kernel<<<eb, TB>>>(adj);

    gemm1_kernel<<<NN / 16, TB>>>(x, W1);
    alpha1_kernel<<<(NN * 32 + TB - 1) / TB, TB>>>(x);
    edge1_exp_kernel<<<eb, TB>>>();
    agg1_kernel<<<(NN * 64 + TB - 1) / TB, TB>>>(b1);

    gemm2_kernel<<<NN / 8, TB>>>(W2, a2_src, a2_dst);
    edge2_exp_kernel<<<eb, TB>>>();
    agg2_lsm_kernel<<<(NN * 32 + TB - 1) / TB, TB>>>(b2, batch);

    final_kernel<<<1, 64>>>(lin_W, lin_b, out);
}

// round 6
// speedup vs baseline: 1.0556x; 1.0556x over previous
#include <cuda_runtime.h>
#include <cuda_fp16.h>
#include <math.h>

#define NN 50000
#define EE 800000
#define ET (EE + NN)
#define GG 64
#define F_IN 128
#define H1DIM 256   // HEADS * HID
#define H2DIM 32
#define NEG_SLOPE 0.2f

// ---------------- scratch ----------------
__device__ __align__(16) __half g_h1[NN * H1DIM];   // fp16 layer1 features
__device__ __align__(16) float g_out1[NN * H1DIM];
__device__ __align__(16) float g_as1[NN * 4];
__device__ __align__(16) float g_ad1[NN * 4];
__device__ __align__(16) float g_ex1[ET * 4];
__device__ __align__(16) __half g_h2[NN * H2DIM];   // fp16 layer2 features
__device__ float g_as2[NN];
__device__ float g_ad2[NN];
__device__ float g_ex2[ET];
__device__ float g_pool[GG * H2DIM];
__device__ float g_cnt[GG];
__device__ int g_deg[NN];          // zeroed by scatter for next replay
__device__ int g_cur[NN];
__device__ int g_off[NN + 1];
__device__ int g_csr_src[ET];
__device__ int g_csr_dst[ET];
__device__ __align__(16) float g_wsd1[F_IN * 8];   // [f][s0..s3,d0..d3]

// ---------------- helpers ----------------
__device__ __forceinline__ float leaky(float e) {
    return (e >= 0.f) ? e : NEG_SLOPE * e;
}
__device__ __forceinline__ unsigned long long pack2(float a, float b) {
    unsigned long long r;
    asm("mov.b64 %0, {%1, %2};" : "=l"(r) : "f"(a), "f"(b));
    return r;
}
__device__ __forceinline__ void unpack2(unsigned long long v, float& a, float& b) {
    asm("mov.b64 {%0, %1}, %2;" : "=f"(a), "=f"(b) : "l"(v));
}
__device__ __forceinline__ void fma2(unsigned long long& acc, unsigned long long a, unsigned long long b) {
    asm("fma.rn.f32x2 %0, %1, %2, %0;" : "+l"(acc) : "l"(a), "l"(b));
}

// ---------------- prep: folded attention vectors + zero pool ----------------
__global__ void prep_kernel(const float* __restrict__ W1,
                            const float* __restrict__ a1s, const float* __restrict__ a1d) {
    int tid = threadIdx.x;  // 1024
    {
        int f = tid >> 3, o = tid & 7;
        int h = o & 3, sd = o >> 2;
        const float* a = sd ? a1d : a1s;
        float s = 0.f;
#pragma unroll 8
        for (int d = 0; d < 64; d++) s += W1[f * H1DIM + h * 64 + d] * a[h * 64 + d];
        g_wsd1[f * 8 + o] = s;
    }
    for (int j = tid; j < GG * H2DIM; j += 1024) g_pool[j] = 0.f;
    if (tid < GG) g_cnt[tid] = 0.f;
}

// ---------------- CSR build ----------------
__global__ void hist_kernel(const int* __restrict__ adj) {
    int e = blockIdx.x * blockDim.x + threadIdx.x;
    if (e >= ET) return;
    int dst = (e < EE) ? adj[EE + e] : e - EE;
    atomicAdd(&g_deg[dst], 1);
}

__global__ void scan_kernel() {
    __shared__ int part[1024];
    int tid = threadIdx.x;
    const int CH = (NN + 1023) / 1024;
    int start = tid * CH;
    int end = min(start + CH, NN);
    int s = 0;
    for (int i = start; i < end; i++) s += g_deg[i];
    part[tid] = s;
    __syncthreads();
    for (int off = 1; off < 1024; off <<= 1) {
        int v = (tid >= off) ? part[tid - off] : 0;
        __syncthreads();
        part[tid] += v;
        __syncthreads();
    }
    int base = (tid == 0) ? 0 : part[tid - 1];
    for (int i = start; i < end; i++) {
        g_off[i] = base;
        g_cur[i] = base;
        base += g_deg[i];
    }
    if (tid == 1023) g_off[NN] = part[1023];
}

__global__ void scatter_kernel(const int* __restrict__ adj) {
    int gt = blockIdx.x * blockDim.x + threadIdx.x;
    int stride = gridDim.x * blockDim.x;
    for (int j = gt; j < NN; j += stride) g_deg[j] = 0;   // reset for next replay
    if (gt >= ET) return;
    int src, dst;
    if (gt < EE) { src = adj[gt]; dst = adj[EE + gt]; }
    else         { src = dst = gt - EE; }
    int p = atomicAdd(&g_cur[dst], 1);
    g_csr_src[p] = src;
    g_csr_dst[p] = dst;
}

// ---------------- GEMM1: h1 = x @ W1 (50000x128 @ 128x256), f32x2, 2-col blocking ----------------
// block 256 threads: c2 = tid&127 -> cols {2c2, 2c2+1}; rh = tid>>7 -> rows rh*8..+8
__global__ void gemm1_kernel(const float* __restrict__ x, const float* __restrict__ W1) {
    __shared__ float xs[16][F_IN];   // 8KB
    int row0 = blockIdx.x * 16;
    int tid = threadIdx.x;
    const float4* xsrc = (const float4*)(x + row0 * F_IN);
    float4* xdst = (float4*)&xs[0][0];
#pragma unroll
    for (int i = tid; i < 16 * F_IN / 4; i += 256) xdst[i] = xsrc[i];
    __syncthreads();
    int c2 = tid & 127, rh = tid >> 7;
    int c0 = c2 * 2;
    unsigned long long acc0[8], acc1[8];
#pragma unroll
    for (int r = 0; r < 8; r++) { acc0[r] = 0ull; acc1[r] = 0ull; }
#pragma unroll 4
    for (int k = 0; k < F_IN; k += 2) {
        float2 w0 = *(const float2*)&W1[k * H1DIM + c0];
        float2 w1 = *(const float2*)&W1[(k + 1) * H1DIM + c0];
        unsigned long long wpA = pack2(w0.x, w1.x);
        unsigned long long wpB = pack2(w0.y, w1.y);
#pragma unroll
        for (int r = 0; r < 8; r++) {
            unsigned long long xv = *(const unsigned long long*)&xs[rh * 8 + r][k];
            fma2(acc0[r], xv, wpA);
            fma2(acc1[r], xv, wpB);
        }
    }
#pragma unroll
    for (int r = 0; r < 8; r++) {
        float la, ha, lb, hb;
        unpack2(acc0[r], la, ha);
        unpack2(acc1[r], lb, hb);
        int row = row0 + rh * 8 + r;
        *(half2*)&g_h1[row * H1DIM + c0] = __floats2half2_rn(la + ha, lb + hb);
    }
}

// ---------------- alpha1: as1/ad1 = x @ wsd1 (warp per node) ----------------
__global__ void alpha1_kernel(const float* __restrict__ x) {
    int gt = blockIdx.x * blockDim.x + threadIdx.x;
    int n = gt >> 5, lane = gt & 31;
    if (n >= NN) return;
    float4 xv = ((const float4*)x)[n * 32 + lane];
    float a0 = 0, a1 = 0, a2 = 0, a3 = 0, b0 = 0, b1 = 0, b2 = 0, b3 = 0;
    float xj[4] = {xv.x, xv.y, xv.z, xv.w};
#pragma unroll
    for (int j = 0; j < 4; j++) {
        int f = lane * 4 + j;
        float4 wa = *(const float4*)&g_wsd1[f * 8];
        float4 wb = *(const float4*)&g_wsd1[f * 8 + 4];
        a0 = fmaf(xj[j], wa.x, a0); a1 = fmaf(xj[j], wa.y, a1);
        a2 = fmaf(xj[j], wa.z, a2); a3 = fmaf(xj[j], wa.w, a3);
        b0 = fmaf(xj[j], wb.x, b0); b1 = fmaf(xj[j], wb.y, b1);
        b2 = fmaf(xj[j], wb.z, b2); b3 = fmaf(xj[j], wb.w, b3);
    }
#pragma unroll
    for (int off = 16; off; off >>= 1) {
        a0 += __shfl_xor_sync(0xffffffffu, a0, off);
        a1 += __shfl_xor_sync(0xffffffffu, a1, off);
        a2 += __shfl_xor_sync(0xffffffffu, a2, off);
        a3 += __shfl_xor_sync(0xffffffffu, a3, off);
        b0 += __shfl_xor_sync(0xffffffffu, b0, off);
        b1 += __shfl_xor_sync(0xffffffffu, b1, off);
        b2 += __shfl_xor_sync(0xffffffffu, b2, off);
        b3 += __shfl_xor_sync(0xffffffffu, b3, off);
    }
    if (lane == 0) {
        *(float4*)&g_as1[n * 4] = make_float4(a0, a1, a2, a3);
        *(float4*)&g_ad1[n * 4] = make_float4(b0, b1, b2, b3);
    }
}

// ---------------- edge exp (layer1), CSR order ----------------
__global__ void edge1_exp_kernel() {
    int p = blockIdx.x * blockDim.x + threadIdx.x;
    if (p >= ET) return;
    int src = g_csr_src[p], dst = g_csr_dst[p];
    float4 as = *(const float4*)&g_as1[src * 4];
    float4 ad = *(const float4*)&g_ad1[dst * 4];
    float4 ex;
    ex.x = __expf(leaky(as.x + ad.x));
    ex.y = __expf(leaky(as.y + ad.y));
    ex.z = __expf(leaky(as.z + ad.z));
    ex.w = __expf(leaky(as.w + ad.w));
    *(float4*)&g_ex1[p * 4] = ex;
}

// ---------------- agg1: 32 threads/node, fp16 h1, LDG.128 gathers ----------------
__global__ void agg1_kernel(const float* __restrict__ b1) {
    int gt = blockIdx.x * blockDim.x + threadIdx.x;
    int n = gt >> 5;
    if (n >= NN) return;
    int c = gt & 31;            // owns halves [8c, 8c+8) = head c>>3
    int head = c >> 3;
    int beg = g_off[n], end = g_off[n + 1];
    float acc0 = 0, acc1 = 0, acc2 = 0, acc3 = 0, acc4 = 0, acc5 = 0, acc6 = 0, acc7 = 0;
    float den = 0.f;
    int i = beg;
    for (; i + 2 <= end; i += 2) {
        int s0 = g_csr_src[i], s1 = g_csr_src[i + 1];
        float e0 = g_ex1[i * 4 + head], e1 = g_ex1[(i + 1) * 4 + head];
        uint4 p0 = ((const uint4*)(g_h1 + s0 * H1DIM))[c];
        uint4 p1 = ((const uint4*)(g_h1 + s1 * H1DIM))[c];
        den += e0 + e1;
        float2 f;
        f = __half22float2(*(const half2*)&p0.x); acc0 = fmaf(e0, f.x, acc0); acc1 = fmaf(e0, f.y, acc1);
        f = __half22float2(*(const half2*)&p0.y); acc2 = fmaf(e0, f.x, acc2); acc3 = fmaf(e0, f.y, acc3);
        f = __half22float2(*(const half2*)&p0.z); acc4 = fmaf(e0, f.x, acc4); acc5 = fmaf(e0, f.y, acc5);
        f = __half22float2(*(const half2*)&p0.w); acc6 = fmaf(e0, f.x, acc6); acc7 = fmaf(e0, f.y, acc7);
        f = __half22float2(*(const half2*)&p1.x); acc0 = fmaf(e1, f.x, acc0); acc1 = fmaf(e1, f.y, acc1);
        f = __half22float2(*(const half2*)&p1.y); acc2 = fmaf(e1, f.x, acc2); acc3 = fmaf(e1, f.y, acc3);
        f = __half22float2(*(const half2*)&p1.z); acc4 = fmaf(e1, f.x, acc4); acc5 = fmaf(e1, f.y, acc5);
        f = __half22float2(*(const half2*)&p1.w); acc6 = fmaf(e1, f.x, acc6); acc7 = fmaf(e1, f.y, acc7);
    }
    if (i < end) {
        int s0 = g_csr_src[i];
        float e0 = g_ex1[i * 4 + head];
        uint4 p0 = ((const uint4*)(g_h1 + s0 * H1DIM))[c];
        den += e0;
        float2 f;
        f = __half22float2(*(const half2*)&p0.x); acc0 = fmaf(e0, f.x, acc0); acc1 = fmaf(e0, f.y, acc1);
        f = __half22float2(*(const half2*)&p0.y); acc2 = fmaf(e0, f.x, acc2); acc3 = fmaf(e0, f.y, acc3);
        f = __half22float2(*(const half2*)&p0.z); acc4 = fmaf(e0, f.x, acc4); acc5 = fmaf(e0, f.y, acc5);
        f = __half22float2(*(const half2*)&p0.w); acc6 = fmaf(e0, f.x, acc6); acc7 = fmaf(e0, f.y, acc7);
    }
    float inv = __fdividef(1.0f, den);
    float4 ba = ((const float4*)b1)[c * 2];
    float4 bb = ((const float4*)b1)[c * 2 + 1];
    float4 o0, o1;
    o0.x = fmaxf(fmaf(acc0, inv, ba.x), 0.f);
    o0.y = fmaxf(fmaf(acc1, inv, ba.y), 0.f);
    o0.z = fmaxf(fmaf(acc2, inv, ba.z), 0.f);
    o0.w = fmaxf(fmaf(acc3, inv, ba.w), 0.f);
    o1.x = fmaxf(fmaf(acc4, inv, bb.x), 0.f);
    o1.y = fmaxf(fmaf(acc5, inv, bb.y), 0.f);
    o1.z = fmaxf(fmaf(acc6, inv, bb.z), 0.f);
    o1.w = fmaxf(fmaf(acc7, inv, bb.w), 0.f);
    float4* op = (float4*)&g_out1[n * H1DIM + c * 8];
    op[0] = o0;
    op[1] = o1;
}

// ---------------- GEMM2 + alpha2: h2 = out1 @ W2 (50000x256 @ 256x32), fp16 h2 ----------------
__global__ void gemm2_kernel(const float* __restrict__ W2,
                             const float* __restrict__ a2s,
                             const float* __restrict__ a2d) {
    __shared__ float xs[8][H1DIM];
    int row0 = blockIdx.x * 8;
    int tid = threadIdx.x;
    const float4* xsrc = (const float4*)&g_out1[row0 * H1DIM];
    float4* xdst = (float4*)&xs[0][0];
#pragma unroll
    for (int i = tid; i < 8 * H1DIM / 4; i += 256) xdst[i] = xsrc[i];
    __syncthreads();
    int r = tid >> 5, c = tid & 31;
    unsigned long long acc = 0ull;
#pragma unroll 8
    for (int k = 0; k < H1DIM; k += 2) {
        float w0 = W2[k * H2DIM + c];
        float w1 = W2[(k + 1) * H2DIM + c];
        unsigned long long wp = pack2(w0, w1);
        unsigned long long xv = *(const unsigned long long*)&xs[r][k];
        fma2(acc, xv, wp);
    }
    float lo, hi; unpack2(acc, lo, hi);
    float hval = lo + hi;
    int row = row0 + r;
    // fp16 store: even lanes write half2 (own + partner col)
    float partner = __shfl_xor_sync(0xffffffffu, hval, 1);
    if ((c & 1) == 0)
        *(half2*)&g_h2[row * H2DIM + c] = __floats2half2_rn(hval, partner);
    // fused alpha2
    float ps = hval * a2s[c];
    float pd = hval * a2d[c];
#pragma unroll
    for (int off = 16; off; off >>= 1) {
        ps += __shfl_xor_sync(0xffffffffu, ps, off);
        pd += __shfl_xor_sync(0xffffffffu, pd, off);
    }
    if (c == 0) { g_as2[row] = ps; g_ad2[row] = pd; }
}

// ---------------- edge exp (layer2) ----------------
__global__ void edge2_exp_kernel() {
    int p = blockIdx.x * blockDim.x + threadIdx.x;
    if (p >= ET) return;
    int src = g_csr_src[p], dst = g_csr_dst[p];
    g_ex2[p] = __expf(leaky(g_as2[src] + g_ad2[dst]));
}

// ---------------- agg2 + bias + log_softmax + pool: 16 threads/node ----------------
__global__ void agg2_lsm_kernel(const float* __restrict__ b2, const int* __restrict__ batch) {
    int gt = blockIdx.x * blockDim.x + threadIdx.x;
    int n = gt >> 4;
    if (n >= NN) return;
    int sub = gt & 15;   // owns cols {2sub, 2sub+1}
    int beg = g_off[n], end = g_off[n + 1];
    float ax = 0.f, ay = 0.f, den = 0.f;
    int i = beg;
    for (; i + 2 <= end; i += 2) {
        int s0 = g_csr_src[i], s1 = g_csr_src[i + 1];
        float e0 = g_ex2[i], e1 = g_ex2[i + 1];
        float2 f0 = __half22float2(((const half2*)(g_h2 + s0 * H2DIM))[sub]);
        float2 f1 = __half22float2(((const half2*)(g_h2 + s1 * H2DIM))[sub]);
        den += e0 + e1;
        ax = fmaf(e0, f0.x, fmaf(e1, f1.x, ax));
        ay = fmaf(e0, f0.y, fmaf(e1, f1.y, ay));
    }
    if (i < end) {
        int s0 = g_csr_src[i];
        float e0 = g_ex2[i];
        float2 f0 = __half22float2(((const half2*)(g_h2 + s0 * H2DIM))[sub]);
        den += e0;
        ax = fmaf(e0, f0.x, ax);
        ay = fmaf(e0, f0.y, ay);
    }
    float inv = __fdividef(1.0f, den);
    float v0 = fmaf(ax, inv, b2[sub * 2]);
    float v1 = fmaf(ay, inv, b2[sub * 2 + 1]);
    float mx = fmaxf(v0, v1);
#pragma unroll
    for (int off = 8; off; off >>= 1) mx = fmaxf(mx, __shfl_xor_sync(0xffffffffu, mx, off));
    float s = expf(v0 - mx) + expf(v1 - mx);
#pragma unroll
    for (int off = 8; off; off >>= 1) s += __shfl_xor_sync(0xffffffffu, s, off);
    float lse = mx + logf(s);
    int b = batch[n];
    atomicAdd(&g_pool[b * H2DIM + sub * 2], v0 - lse);
    atomicAdd(&g_pool[b * H2DIM + sub * 2 + 1], v1 - lse);
    if (sub == 0) atomicAdd(&g_cnt[b], 1.0f);
}

// ---------------- final ----------------
__global__ void final_kernel(const float* __restrict__ lin_W, const float* __restrict__ lin_b,
                             float* __restrict__ out) {
    int g = threadIdx.x;
    if (g >= GG) return;
    float inv = 1.0f / fmaxf(g_cnt[g], 1.0f);
    float acc = lin_b[0];
#pragma unroll
    for (int j = 0; j < H2DIM; j++) acc += g_pool[g * H2DIM + j] * inv * lin_W[j];
    out[g] = acc;
}

// ---------------- launcher ----------------
extern "C" void kernel_launch(void* const* d_in, const int* in_sizes, int n_in,
                              void* d_out, int out_size) {
    const float* x      = (const float*)d_in[0];
    const int*   adj    = (const int*)d_in[1];
    const int*   batch  = (const int*)d_in[2];
    const float* W1     = (const float*)d_in[3];
    const float* a1_src = (const float*)d_in[4];
    const float* a1_dst = (const float*)d_in[5];
    const float* b1     = (const float*)d_in[6];
    const float* W2     = (const float*)d_in[7];
    const float* a2_src = (const float*)d_in[8];
    const float* a2_dst = (const float*)d_in[9];
    const float* b2     = (const float*)d_in[10];
    const float* lin_W  = (const float*)d_in[11];
    const float* lin_b  = (const float*)d_in[12];
    float* out = (float*)d_out;

    const int TB = 256;
    int eb = (ET + TB - 1) / TB;

    prep_kernel<<<1, 1024>>>(W1, a1_src, a1_dst);
    hist_kernel<<<eb, TB>>>(adj);
    scan_kernel<<<1, 1024>>>();
    scatter_kernel<<<eb, TB>>>(adj);

    gemm1_kernel<<<NN / 16, TB>>>(x, W1);
    alpha1_kernel<<<(NN * 32 + TB - 1) / TB, TB>>>(x);
    edge1_exp_kernel<<<eb, TB>>>();
    agg1_kernel<<<(NN * 32 + TB - 1) / TB, TB>>>(b1);

    gemm2_kernel<<<NN / 8, TB>>>(W2, a2_src, a2_dst);
    edge2_exp_kernel<<<eb, TB>>>();
    agg2_lsm_kernel<<<(NN * 16 + TB - 1) / TB, TB>>>(b2, batch);

    final_kernel<<<1, 64>>>(lin_W, lin_b, out);
}

// round 7
// speedup vs baseline: 1.1656x; 1.1042x over previous
#include <cuda_runtime.h>
#include <cuda_fp16.h>
#include <math.h>

#define NN 50000
#define EE 800000
#define ET (EE + NN)
#define GG 64
#define F_IN 128
#define H1DIM 256   // HEADS * HID
#define H2DIM 32
#define NEG_SLOPE 0.2f

// ---------------- scratch ----------------
__device__ __align__(16) __half g_h1[NN * H1DIM];   // fp16 layer1 features
__device__ __align__(16) float g_out1[NN * H1DIM];
__device__ __align__(16) float g_as1[NN * 4];
__device__ __align__(16) float g_ad1[NN * 4];
__device__ __align__(16) float g_ex1[ET * 4];
__device__ __align__(16) __half g_h2[NN * H2DIM];   // fp16 layer2 features
__device__ float g_as2[NN];
__device__ float g_ad2[NN];
__device__ float g_ex2[ET];
__device__ float g_pool[GG * H2DIM];
__device__ float g_cnt[GG];
__device__ int g_deg[NN];          // zeroed by scatter for next replay
__device__ int g_cur[NN];
__device__ int g_off[NN + 1];
__device__ int g_csr_src[ET];
__device__ int g_csr_dst[ET];
__device__ __align__(16) float g_wsd1[F_IN * 8];   // [f][s0..s3,d0..d3]

// ---------------- helpers ----------------
__device__ __forceinline__ float leaky(float e) {
    return (e >= 0.f) ? e : NEG_SLOPE * e;
}
__device__ __forceinline__ unsigned long long pack2(float a, float b) {
    unsigned long long r;
    asm("mov.b64 %0, {%1, %2};" : "=l"(r) : "f"(a), "f"(b));
    return r;
}
__device__ __forceinline__ void unpack2(unsigned long long v, float& a, float& b) {
    asm("mov.b64 {%0, %1}, %2;" : "=f"(a), "=f"(b) : "l"(v));
}
__device__ __forceinline__ void fma2(unsigned long long& acc, unsigned long long a, unsigned long long b) {
    asm("fma.rn.f32x2 %0, %1, %2, %0;" : "+l"(acc) : "l"(a), "l"(b));
}

// ---------------- prep: folded attention vectors + zero pool ----------------
__global__ void prep_kernel(const float* __restrict__ W1,
                            const float* __restrict__ a1s, const float* __restrict__ a1d) {
    int tid = threadIdx.x;  // 1024
    {
        int f = tid >> 3, o = tid & 7;
        int h = o & 3, sd = o >> 2;
        const float* a = sd ? a1d : a1s;
        float s = 0.f;
#pragma unroll 8
        for (int d = 0; d < 64; d++) s += W1[f * H1DIM + h * 64 + d] * a[h * 64 + d];
        g_wsd1[f * 8 + o] = s;
    }
    for (int j = tid; j < GG * H2DIM; j += 1024) g_pool[j] = 0.f;
    if (tid < GG) g_cnt[tid] = 0.f;
}

// ---------------- CSR build ----------------
__global__ void hist_kernel(const int* __restrict__ adj) {
    int e = blockIdx.x * blockDim.x + threadIdx.x;
    if (e >= ET) return;
    int dst = (e < EE) ? adj[EE + e] : e - EE;
    atomicAdd(&g_deg[dst], 1);
}

// coalesced multi-round block scan: 1024 threads, rounds of 1024 elements
__global__ void scan_kernel() {
    __shared__ int warpsum[32];
    int tid = threadIdx.x;
    int lane = tid & 31, wid = tid >> 5;
    int running = 0;
    for (int base = 0; base < NN; base += 1024) {
        int i = base + tid;
        int v = (i < NN) ? g_deg[i] : 0;
        // warp inclusive scan
        int val = v;
#pragma unroll
        for (int off = 1; off < 32; off <<= 1) {
            int t = __shfl_up_sync(0xffffffffu, val, off);
            if (lane >= off) val += t;
        }
        if (lane == 31) warpsum[wid] = val;
        __syncthreads();
        if (wid == 0) {
            int s = warpsum[lane];
#pragma unroll
            for (int off = 1; off < 32; off <<= 1) {
                int t = __shfl_up_sync(0xffffffffu, s, off);
                if (lane >= off) s += t;
            }
            warpsum[lane] = s;  // inclusive warp sums
        }
        __syncthreads();
        int warpbase = (wid == 0) ? 0 : warpsum[wid - 1];
        int excl = running + warpbase + val - v;
        if (i < NN) { g_off[i] = excl; g_cur[i] = excl; }
        running += warpsum[31];
        __syncthreads();  // protect warpsum before next round overwrites
    }
    if (tid == 0) g_off[NN] = running;
}

__global__ void scatter_kernel(const int* __restrict__ adj) {
    int gt = blockIdx.x * blockDim.x + threadIdx.x;
    int stride = gridDim.x * blockDim.x;
    for (int j = gt; j < NN; j += stride) g_deg[j] = 0;   // reset for next replay
    if (gt >= ET) return;
    int src, dst;
    if (gt < EE) { src = adj[gt]; dst = adj[EE + gt]; }
    else         { src = dst = gt - EE; }
    int p = atomicAdd(&g_cur[dst], 1);
    g_csr_src[p] = src;
    g_csr_dst[p] = dst;
}

// ---------------- GEMM1: h1 = x @ W1 (50000x128 @ 128x256), f32x2, 2-col blocking ----------------
__global__ void gemm1_kernel(const float* __restrict__ x, const float* __restrict__ W1) {
    __shared__ float xs[16][F_IN];   // 8KB
    int row0 = blockIdx.x * 16;
    int tid = threadIdx.x;
    const float4* xsrc = (const float4*)(x + row0 * F_IN);
    float4* xdst = (float4*)&xs[0][0];
#pragma unroll
    for (int i = tid; i < 16 * F_IN / 4; i += 256) xdst[i] = xsrc[i];
    __syncthreads();
    int c2 = tid & 127, rh = tid >> 7;
    int c0 = c2 * 2;
    unsigned long long acc0[8], acc1[8];
#pragma unroll
    for (int r = 0; r < 8; r++) { acc0[r] = 0ull; acc1[r] = 0ull; }
#pragma unroll 2
    for (int k = 0; k < F_IN; k += 4) {
        float2 w0 = *(const float2*)&W1[k * H1DIM + c0];
        float2 w1 = *(const float2*)&W1[(k + 1) * H1DIM + c0];
        float2 w2 = *(const float2*)&W1[(k + 2) * H1DIM + c0];
        float2 w3 = *(const float2*)&W1[(k + 3) * H1DIM + c0];
        unsigned long long wpA0 = pack2(w0.x, w1.x);
        unsigned long long wpB0 = pack2(w0.y, w1.y);
        unsigned long long wpA1 = pack2(w2.x, w3.x);
        unsigned long long wpB1 = pack2(w2.y, w3.y);
#pragma unroll
        for (int r = 0; r < 8; r++) {
            float4 xv = *(const float4*)&xs[rh * 8 + r][k];   // LDS.128
            unsigned long long x01 = pack2(xv.x, xv.y);
            unsigned long long x23 = pack2(xv.z, xv.w);
            fma2(acc0[r], x01, wpA0);
            fma2(acc1[r], x01, wpB0);
            fma2(acc0[r], x23, wpA1);
            fma2(acc1[r], x23, wpB1);
        }
    }
#pragma unroll
    for (int r = 0; r < 8; r++) {
        float la, ha, lb, hb;
        unpack2(acc0[r], la, ha);
        unpack2(acc1[r], lb, hb);
        int row = row0 + rh * 8 + r;
        *(half2*)&g_h1[row * H1DIM + c0] = __floats2half2_rn(la + ha, lb + hb);
    }
}

// ---------------- alpha1: as1/ad1 = x @ wsd1 (warp per node) ----------------
__global__ void alpha1_kernel(const float* __restrict__ x) {
    int gt = blockIdx.x * blockDim.x + threadIdx.x;
    int n = gt >> 5, lane = gt & 31;
    if (n >= NN) return;
    float4 xv = ((const float4*)x)[n * 32 + lane];
    float a0 = 0, a1 = 0, a2 = 0, a3 = 0, b0 = 0, b1 = 0, b2 = 0, b3 = 0;
    float xj[4] = {xv.x, xv.y, xv.z, xv.w};
#pragma unroll
    for (int j = 0; j < 4; j++) {
        int f = lane * 4 + j;
        float4 wa = *(const float4*)&g_wsd1[f * 8];
        float4 wb = *(const float4*)&g_wsd1[f * 8 + 4];
        a0 = fmaf(xj[j], wa.x, a0); a1 = fmaf(xj[j], wa.y, a1);
        a2 = fmaf(xj[j], wa.z, a2); a3 = fmaf(xj[j], wa.w, a3);
        b0 = fmaf(xj[j], wb.x, b0); b1 = fmaf(xj[j], wb.y, b1);
        b2 = fmaf(xj[j], wb.z, b2); b3 = fmaf(xj[j], wb.w, b3);
    }
#pragma unroll
    for (int off = 16; off; off >>= 1) {
        a0 += __shfl_xor_sync(0xffffffffu, a0, off);
        a1 += __shfl_xor_sync(0xffffffffu, a1, off);
        a2 += __shfl_xor_sync(0xffffffffu, a2, off);
        a3 += __shfl_xor_sync(0xffffffffu, a3, off);
        b0 += __shfl_xor_sync(0xffffffffu, b0, off);
        b1 += __shfl_xor_sync(0xffffffffu, b1, off);
        b2 += __shfl_xor_sync(0xffffffffu, b2, off);
        b3 += __shfl_xor_sync(0xffffffffu, b3, off);
    }
    if (lane == 0) {
        *(float4*)&g_as1[n * 4] = make_float4(a0, a1, a2, a3);
        *(float4*)&g_ad1[n * 4] = make_float4(b0, b1, b2, b3);
    }
}

// ---------------- edge exp (layer1), CSR order ----------------
__global__ void edge1_exp_kernel() {
    int p = blockIdx.x * blockDim.x + threadIdx.x;
    if (p >= ET) return;
    int src = g_csr_src[p], dst = g_csr_dst[p];
    float4 as = *(const float4*)&g_as1[src * 4];
    float4 ad = *(const float4*)&g_ad1[dst * 4];
    float4 ex;
    ex.x = __expf(leaky(as.x + ad.x));
    ex.y = __expf(leaky(as.y + ad.y));
    ex.z = __expf(leaky(as.z + ad.z));
    ex.w = __expf(leaky(as.w + ad.w));
    *(float4*)&g_ex1[p * 4] = ex;
}

// ---------------- agg1: 32 threads/node, fp16 h1, LDG.128 gathers ----------------
__global__ void agg1_kernel(const float* __restrict__ b1) {
    int gt = blockIdx.x * blockDim.x + threadIdx.x;
    int n = gt >> 5;
    if (n >= NN) return;
    int c = gt & 31;            // owns halves [8c, 8c+8) = head c>>3
    int head = c >> 3;
    int beg = g_off[n], end = g_off[n + 1];
    float acc0 = 0, acc1 = 0, acc2 = 0, acc3 = 0, acc4 = 0, acc5 = 0, acc6 = 0, acc7 = 0;
    float den = 0.f;
    int i = beg;
    for (; i + 2 <= end; i += 2) {
        int s0 = g_csr_src[i], s1 = g_csr_src[i + 1];
        float e0 = g_ex1[i * 4 + head], e1 = g_ex1[(i + 1) * 4 + head];
        uint4 p0 = ((const uint4*)(g_h1 + s0 * H1DIM))[c];
        uint4 p1 = ((const uint4*)(g_h1 + s1 * H1DIM))[c];
        den += e0 + e1;
        float2 f;
        f = __half22float2(*(const half2*)&p0.x); acc0 = fmaf(e0, f.x, acc0); acc1 = fmaf(e0, f.y, acc1);
        f = __half22float2(*(const half2*)&p0.y); acc2 = fmaf(e0, f.x, acc2); acc3 = fmaf(e0, f.y, acc3);
        f = __half22float2(*(const half2*)&p0.z); acc4 = fmaf(e0, f.x, acc4); acc5 = fmaf(e0, f.y, acc5);
        f = __half22float2(*(const half2*)&p0.w); acc6 = fmaf(e0, f.x, acc6); acc7 = fmaf(e0, f.y, acc7);
        f = __half22float2(*(const half2*)&p1.x); acc0 = fmaf(e1, f.x, acc0); acc1 = fmaf(e1, f.y, acc1);
        f = __half22float2(*(const half2*)&p1.y); acc2 = fmaf(e1, f.x, acc2); acc3 = fmaf(e1, f.y, acc3);
        f = __half22float2(*(const half2*)&p1.z); acc4 = fmaf(e1, f.x, acc4); acc5 = fmaf(e1, f.y, acc5);
        f = __half22float2(*(const half2*)&p1.w); acc6 = fmaf(e1, f.x, acc6); acc7 = fmaf(e1, f.y, acc7);
    }
    if (i < end) {
        int s0 = g_csr_src[i];
        float e0 = g_ex1[i * 4 + head];
        uint4 p0 = ((const uint4*)(g_h1 + s0 * H1DIM))[c];
        den += e0;
        float2 f;
        f = __half22float2(*(const half2*)&p0.x); acc0 = fmaf(e0, f.x, acc0); acc1 = fmaf(e0, f.y, acc1);
        f = __half22float2(*(const half2*)&p0.y); acc2 = fmaf(e0, f.x, acc2); acc3 = fmaf(e0, f.y, acc3);
        f = __half22float2(*(const half2*)&p0.z); acc4 = fmaf(e0, f.x, acc4); acc5 = fmaf(e0, f.y, acc5);
        f = __half22float2(*(const half2*)&p0.w); acc6 = fmaf(e0, f.x, acc6); acc7 = fmaf(e0, f.y, acc7);
    }
    float inv = __fdividef(1.0f, den);
    float4 ba = ((const float4*)b1)[c * 2];
    float4 bb = ((const float4*)b1)[c * 2 + 1];
    float4 o0, o1;
    o0.x = fmaxf(fmaf(acc0, inv, ba.x), 0.f);
    o0.y = fmaxf(fmaf(acc1, inv, ba.y), 0.f);
    o0.z = fmaxf(fmaf(acc2, inv, ba.z), 0.f);
    o0.w = fmaxf(fmaf(acc3, inv, ba.w), 0.f);
    o1.x = fmaxf(fmaf(acc4, inv, bb.x), 0.f);
    o1.y = fmaxf(fmaf(acc5, inv, bb.y), 0.f);
    o1.z = fmaxf(fmaf(acc6, inv, bb.z), 0.f);
    o1.w = fmaxf(fmaf(acc7, inv, bb.w), 0.f);
    float4* op = (float4*)&g_out1[n * H1DIM + c * 8];
    op[0] = o0;
    op[1] = o1;
}

// ---------------- GEMM2 + alpha2: h2 = out1 @ W2 (50000x256 @ 256x32), fp16 h2 ----------------
__global__ void gemm2_kernel(const float* __restrict__ W2,
                             const float* __restrict__ a2s,
                             const float* __restrict__ a2d) {
    __shared__ float xs[8][H1DIM];
    int row0 = blockIdx.x * 8;
    int tid = threadIdx.x;
    const float4* xsrc = (const float4*)&g_out1[row0 * H1DIM];
    float4* xdst = (float4*)&xs[0][0];
#pragma unroll
    for (int i = tid; i < 8 * H1DIM / 4; i += 256) xdst[i] = xsrc[i];
    __syncthreads();
    int r = tid >> 5, c = tid & 31;
    unsigned long long acc = 0ull;
#pragma unroll 4
    for (int k = 0; k < H1DIM; k += 4) {
        float w0 = W2[k * H2DIM + c];
        float w1 = W2[(k + 1) * H2DIM + c];
        float w2 = W2[(k + 2) * H2DIM + c];
        float w3 = W2[(k + 3) * H2DIM + c];
        float4 xv = *(const float4*)&xs[r][k];   // LDS.128
        fma2(acc, pack2(xv.x, xv.y), pack2(w0, w1));
        fma2(acc, pack2(xv.z, xv.w), pack2(w2, w3));
    }
    float lo, hi; unpack2(acc, lo, hi);
    float hval = lo + hi;
    int row = row0 + r;
    float partner = __shfl_xor_sync(0xffffffffu, hval, 1);
    if ((c & 1) == 0)
        *(half2*)&g_h2[row * H2DIM + c] = __floats2half2_rn(hval, partner);
    // fused alpha2
    float ps = hval * a2s[c];
    float pd = hval * a2d[c];
#pragma unroll
    for (int off = 16; off; off >>= 1) {
        ps += __shfl_xor_sync(0xffffffffu, ps, off);
        pd += __shfl_xor_sync(0xffffffffu, pd, off);
    }
    if (c == 0) { g_as2[row] = ps; g_ad2[row] = pd; }
}

// ---------------- edge exp (layer2) ----------------
__global__ void edge2_exp_kernel() {
    int p = blockIdx.x * blockDim.x + threadIdx.x;
    if (p >= ET) return;
    int src = g_csr_src[p], dst = g_csr_dst[p];
    g_ex2[p] = __expf(leaky(g_as2[src] + g_ad2[dst]));
}

// ---------------- agg2 + bias + log_softmax + pool: 16 threads/node ----------------
__global__ void agg2_lsm_kernel(const float* __restrict__ b2, const int* __restrict__ batch) {
    int gt = blockIdx.x * blockDim.x + threadIdx.x;
    int n = gt >> 4;
    if (n >= NN) return;
    int sub = gt & 15;   // owns cols {2sub, 2sub+1}
    int beg = g_off[n], end = g_off[n + 1];
    float ax = 0.f, ay = 0.f, den = 0.f;
    int i = beg;
    for (; i + 2 <= end; i += 2) {
        int s0 = g_csr_src[i], s1 = g_csr_src[i + 1];
        float e0 = g_ex2[i], e1 = g_ex2[i + 1];
        float2 f0 = __half22float2(((const half2*)(g_h2 + s0 * H2DIM))[sub]);
        float2 f1 = __half22float2(((const half2*)(g_h2 + s1 * H2DIM))[sub]);
        den += e0 + e1;
        ax = fmaf(e0, f0.x, fmaf(e1, f1.x, ax));
        ay = fmaf(e0, f0.y, fmaf(e1, f1.y, ay));
    }
    if (i < end) {
        int s0 = g_csr_src[i];
        float e0 = g_ex2[i];
        float2 f0 = __half22float2(((const half2*)(g_h2 + s0 * H2DIM))[sub]);
        den += e0;
        ax = fmaf(e0, f0.x, ax);
        ay = fmaf(e0, f0.y, ay);
    }
    float inv = __fdividef(1.0f, den);
    float v0 = fmaf(ax, inv, b2[sub * 2]);
    float v1 = fmaf(ay, inv, b2[sub * 2 + 1]);
    float mx = fmaxf(v0, v1);
#pragma unroll
    for (int off = 8; off; off >>= 1) mx = fmaxf(mx, __shfl_xor_sync(0xffffffffu, mx, off));
    float s = expf(v0 - mx) + expf(v1 - mx);
#pragma unroll
    for (int off = 8; off; off >>= 1) s += __shfl_xor_sync(0xffffffffu, s, off);
    float lse = mx + logf(s);
    int b = batch[n];
    atomicAdd(&g_pool[b * H2DIM + sub * 2], v0 - lse);
    atomicAdd(&g_pool[b * H2DIM + sub * 2 + 1], v1 - lse);
    if (sub == 0) atomicAdd(&g_cnt[b], 1.0f);
}

// ---------------- final ----------------
__global__ void final_kernel(const float* __restrict__ lin_W, const float* __restrict__ lin_b,
                             float* __restrict__ out) {
    int g = threadIdx.x;
    if (g >= GG) return;
    float inv = 1.0f / fmaxf(g_cnt[g], 1.0f);
    float acc = lin_b[0];
#pragma unroll
    for (int j = 0; j < H2DIM; j++) acc += g_pool[g * H2DIM + j] * inv * lin_W[j];
    out[g] = acc;
}

// ---------------- launcher ----------------
extern "C" void kernel_launch(void* const* d_in, const int* in_sizes, int n_in,
                              void* d_out, int out_size) {
    const float* x      = (const float*)d_in[0];
    const int*   adj    = (const int*)d_in[1];
    const int*   batch  = (const int*)d_in[2];
    const float* W1     = (const float*)d_in[3];
    const float* a1_src = (const float*)d_in[4];
    const float* a1_dst = (const float*)d_in[5];
    const float* b1     = (const float*)d_in[6];
    const float* W2     = (const float*)d_in[7];
    const float* a2_src = (const float*)d_in[8];
    const float* a2_dst = (const float*)d_in[9];
    const float* b2     = (const float*)d_in[10];
    const float* lin_W  = (const float*)d_in[11];
    const float* lin_b  = (const float*)d_in[12];
    float* out = (float*)d_out;

    const int TB = 256;
    int eb = (ET + TB - 1) / TB;

    prep_kernel<<<1, 1024>>>(W1, a1_src, a1_dst);
    hist_kernel<<<eb, TB>>>(adj);
    scan_kernel<<<1, 1024>>>();
    scatter_kernel<<<eb, TB>>>(adj);

    gemm1_kernel<<<NN / 16, TB>>>(x, W1);
    alpha1_kernel<<<(NN * 32 + TB - 1) / TB, TB>>>(x);
    edge1_exp_kernel<<<eb, TB>>>();
    agg1_kernel<<<(NN * 32 + TB - 1) / TB, TB>>>(b1);

    gemm2_kernel<<<NN / 8, TB>>>(W2, a2_src, a2_dst);
    edge2_exp_kernel<<<eb, TB>>>();
    agg2_lsm_kernel<<<(NN * 16 + TB - 1) / TB, TB>>>(b2, batch);

    final_kernel<<<1, 64>>>(lin_W, lin_b, out);
}

// round 8
// speedup vs baseline: 1.1866x; 1.0180x over previous
#include <cuda_runtime.h>
#include <cuda_fp16.h>
#include <math.h>

#define NN 50000
#define EE 800000
#define ET (EE + NN)
#define GG 64
#define F_IN 128
#define H1DIM 256   // HEADS * HID
#define H2DIM 32
#define NEG_SLOPE 0.2f

// ---------------- scratch ----------------
__device__ __align__(16) __half g_h1[NN * H1DIM];   // fp16 layer1 features
__device__ __align__(16) float g_out1[NN * H1DIM];
__device__ __align__(16) float g_as1[NN * 4];
__device__ __align__(16) float g_ad1[NN * 4];
__device__ __align__(16) __half g_h2[NN * H2DIM];   // fp16 layer2 features
__device__ float g_as2[NN];
__device__ float g_ad2[NN];
__device__ float g_pool[GG * H2DIM];
__device__ float g_cnt[GG];
__device__ int g_deg[NN];          // zeroed by scatter for next replay
__device__ int g_cur[NN];
__device__ int g_off[NN + 1];
__device__ int g_csr_src[ET];
__device__ __align__(16) float g_wsd1[F_IN * 8];   // [f][s0..s3,d0..d3]

// ---------------- helpers ----------------
__device__ __forceinline__ float leaky(float e) {
    return (e >= 0.f) ? e : NEG_SLOPE * e;
}
__device__ __forceinline__ unsigned long long pack2(float a, float b) {
    unsigned long long r;
    asm("mov.b64 %0, {%1, %2};" : "=l"(r) : "f"(a), "f"(b));
    return r;
}
__device__ __forceinline__ void unpack2(unsigned long long v, float& a, float& b) {
    asm("mov.b64 {%0, %1}, %2;" : "=f"(a), "=f"(b) : "l"(v));
}
__device__ __forceinline__ void fma2(unsigned long long& acc, unsigned long long a, unsigned long long b) {
    asm("fma.rn.f32x2 %0, %1, %2, %0;" : "+l"(acc) : "l"(a), "l"(b));
}

// ---------------- prep: folded attention vectors + zero pool ----------------
__global__ void prep_kernel(const float* __restrict__ W1,
                            const float* __restrict__ a1s, const float* __restrict__ a1d) {
    int tid = threadIdx.x;  // 1024
    {
        int f = tid >> 3, o = tid & 7;
        int h = o & 3, sd = o >> 2;
        const float* a = sd ? a1d : a1s;
        float s = 0.f;
#pragma unroll 8
        for (int d = 0; d < 64; d++) s += W1[f * H1DIM + h * 64 + d] * a[h * 64 + d];
        g_wsd1[f * 8 + o] = s;
    }
    for (int j = tid; j < GG * H2DIM; j += 1024) g_pool[j] = 0.f;
    if (tid < GG) g_cnt[tid] = 0.f;
}

// ---------------- CSR build ----------------
__global__ void hist_kernel(const int* __restrict__ adj) {
    int e = blockIdx.x * blockDim.x + threadIdx.x;
    if (e >= ET) return;
    int dst = (e < EE) ? adj[EE + e] : e - EE;
    atomicAdd(&g_deg[dst], 1);
}

// coalesced multi-round block scan: 1024 threads, rounds of 1024 elements
__global__ void scan_kernel() {
    __shared__ int warpsum[32];
    int tid = threadIdx.x;
    int lane = tid & 31, wid = tid >> 5;
    int running = 0;
    for (int base = 0; base < NN; base += 1024) {
        int i = base + tid;
        int v = (i < NN) ? g_deg[i] : 0;
        int val = v;
#pragma unroll
        for (int off = 1; off < 32; off <<= 1) {
            int t = __shfl_up_sync(0xffffffffu, val, off);
            if (lane >= off) val += t;
        }
        if (lane == 31) warpsum[wid] = val;
        __syncthreads();
        if (wid == 0) {
            int s = warpsum[lane];
#pragma unroll
            for (int off = 1; off < 32; off <<= 1) {
                int t = __shfl_up_sync(0xffffffffu, s, off);
                if (lane >= off) s += t;
            }
            warpsum[lane] = s;
        }
        __syncthreads();
        int warpbase = (wid == 0) ? 0 : warpsum[wid - 1];
        int excl = running + warpbase + val - v;
        if (i < NN) { g_off[i] = excl; g_cur[i] = excl; }
        running += warpsum[31];
        __syncthreads();
    }
    if (tid == 0) g_off[NN] = running;
}

__global__ void scatter_kernel(const int* __restrict__ adj) {
    int gt = blockIdx.x * blockDim.x + threadIdx.x;
    int stride = gridDim.x * blockDim.x;
    for (int j = gt; j < NN; j += stride) g_deg[j] = 0;   // reset for next replay
    if (gt >= ET) return;
    int src, dst;
    if (gt < EE) { src = adj[gt]; dst = adj[EE + gt]; }
    else         { src = dst = gt - EE; }
    int p = atomicAdd(&g_cur[dst], 1);
    g_csr_src[p] = src;
}

// ---------------- GEMM1: h1 = x @ W1 (50000x128 @ 128x256), f32x2, 2-col blocking ----------------
__global__ void gemm1_kernel(const float* __restrict__ x, const float* __restrict__ W1) {
    __shared__ float xs[16][F_IN];   // 8KB
    int row0 = blockIdx.x * 16;
    int tid = threadIdx.x;
    const float4* xsrc = (const float4*)(x + row0 * F_IN);
    float4* xdst = (float4*)&xs[0][0];
#pragma unroll
    for (int i = tid; i < 16 * F_IN / 4; i += 256) xdst[i] = xsrc[i];
    __syncthreads();
    int c2 = tid & 127, rh = tid >> 7;
    int c0 = c2 * 2;
    unsigned long long acc0[8], acc1[8];
#pragma unroll
    for (int r = 0; r < 8; r++) { acc0[r] = 0ull; acc1[r] = 0ull; }
#pragma unroll 4
    for (int k = 0; k < F_IN; k += 2) {
        float2 w0 = *(const float2*)&W1[k * H1DIM + c0];
        float2 w1 = *(const float2*)&W1[(k + 1) * H1DIM + c0];
        unsigned long long wpA = pack2(w0.x, w1.x);
        unsigned long long wpB = pack2(w0.y, w1.y);
#pragma unroll
        for (int r = 0; r < 8; r++) {
            unsigned long long xv = *(const unsigned long long*)&xs[rh * 8 + r][k];  // LDS.64, pre-paired
            fma2(acc0[r], xv, wpA);
            fma2(acc1[r], xv, wpB);
        }
    }
#pragma unroll
    for (int r = 0; r < 8; r++) {
        float la, ha, lb, hb;
        unpack2(acc0[r], la, ha);
        unpack2(acc1[r], lb, hb);
        int row = row0 + rh * 8 + r;
        *(half2*)&g_h1[row * H1DIM + c0] = __floats2half2_rn(la + ha, lb + hb);
    }
}

// ---------------- alpha1: as1/ad1 = x @ wsd1 (warp per node) ----------------
__global__ void alpha1_kernel(const float* __restrict__ x) {
    int gt = blockIdx.x * blockDim.x + threadIdx.x;
    int n = gt >> 5, lane = gt & 31;
    if (n >= NN) return;
    float4 xv = ((const float4*)x)[n * 32 + lane];
    float a0 = 0, a1 = 0, a2 = 0, a3 = 0, b0 = 0, b1 = 0, b2 = 0, b3 = 0;
    float xj[4] = {xv.x, xv.y, xv.z, xv.w};
#pragma unroll
    for (int j = 0; j < 4; j++) {
        int f = lane * 4 + j;
        float4 wa = *(const float4*)&g_wsd1[f * 8];
        float4 wb = *(const float4*)&g_wsd1[f * 8 + 4];
        a0 = fmaf(xj[j], wa.x, a0); a1 = fmaf(xj[j], wa.y, a1);
        a2 = fmaf(xj[j], wa.z, a2); a3 = fmaf(xj[j], wa.w, a3);
        b0 = fmaf(xj[j], wb.x, b0); b1 = fmaf(xj[j], wb.y, b1);
        b2 = fmaf(xj[j], wb.z, b2); b3 = fmaf(xj[j], wb.w, b3);
    }
#pragma unroll
    for (int off = 16; off; off >>= 1) {
        a0 += __shfl_xor_sync(0xffffffffu, a0, off);
        a1 += __shfl_xor_sync(0xffffffffu, a1, off);
        a2 += __shfl_xor_sync(0xffffffffu, a2, off);
        a3 += __shfl_xor_sync(0xffffffffu, a3, off);
        b0 += __shfl_xor_sync(0xffffffffu, b0, off);
        b1 += __shfl_xor_sync(0xffffffffu, b1, off);
        b2 += __shfl_xor_sync(0xffffffffu, b2, off);
        b3 += __shfl_xor_sync(0xffffffffu, b3, off);
    }
    if (lane == 0) {
        *(float4*)&g_as1[n * 4] = make_float4(a0, a1, a2, a3);
        *(float4*)&g_ad1[n * 4] = make_float4(b0, b1, b2, b3);
    }
}

// ---------------- agg1: 32 threads/node, inline exp, fp16 h1 LDG.128 gathers ----------------
__global__ void agg1_kernel(const float* __restrict__ b1) {
    int gt = blockIdx.x * blockDim.x + threadIdx.x;
    int n = gt >> 5;
    if (n >= NN) return;
    int c = gt & 31;            // owns halves [8c, 8c+8) = head c>>3
    int head = c >> 3;
    float adh = g_ad1[n * 4 + head];
    int beg = g_off[n], end = g_off[n + 1];
    float acc0 = 0, acc1 = 0, acc2 = 0, acc3 = 0, acc4 = 0, acc5 = 0, acc6 = 0, acc7 = 0;
    float den = 0.f;
    int i = beg;
    for (; i + 2 <= end; i += 2) {
        int s0 = g_csr_src[i], s1 = g_csr_src[i + 1];
        float e0 = __expf(leaky(g_as1[s0 * 4 + head] + adh));
        float e1 = __expf(leaky(g_as1[s1 * 4 + head] + adh));
        uint4 p0 = ((const uint4*)(g_h1 + s0 * H1DIM))[c];
        uint4 p1 = ((const uint4*)(g_h1 + s1 * H1DIM))[c];
        den += e0 + e1;
        float2 f;
        f = __half22float2(*(const half2*)&p0.x); acc0 = fmaf(e0, f.x, acc0); acc1 = fmaf(e0, f.y, acc1);
        f = __half22float2(*(const half2*)&p0.y); acc2 = fmaf(e0, f.x, acc2); acc3 = fmaf(e0, f.y, acc3);
        f = __half22float2(*(const half2*)&p0.z); acc4 = fmaf(e0, f.x, acc4); acc5 = fmaf(e0, f.y, acc5);
        f = __half22float2(*(const half2*)&p0.w); acc6 = fmaf(e0, f.x, acc6); acc7 = fmaf(e0, f.y, acc7);
        f = __half22float2(*(const half2*)&p1.x); acc0 = fmaf(e1, f.x, acc0); acc1 = fmaf(e1, f.y, acc1);
        f = __half22float2(*(const half2*)&p1.y); acc2 = fmaf(e1, f.x, acc2); acc3 = fmaf(e1, f.y, acc3);
        f = __half22float2(*(const half2*)&p1.z); acc4 = fmaf(e1, f.x, acc4); acc5 = fmaf(e1, f.y, acc5);
        f = __half22float2(*(const half2*)&p1.w); acc6 = fmaf(e1, f.x, acc6); acc7 = fmaf(e1, f.y, acc7);
    }
    if (i < end) {
        int s0 = g_csr_src[i];
        float e0 = __expf(leaky(g_as1[s0 * 4 + head] + adh));
        uint4 p0 = ((const uint4*)(g_h1 + s0 * H1DIM))[c];
        den += e0;
        float2 f;
        f = __half22float2(*(const half2*)&p0.x); acc0 = fmaf(e0, f.x, acc0); acc1 = fmaf(e0, f.y, acc1);
        f = __half22float2(*(const half2*)&p0.y); acc2 = fmaf(e0, f.x, acc2); acc3 = fmaf(e0, f.y, acc3);
        f = __half22float2(*(const half2*)&p0.z); acc4 = fmaf(e0, f.x, acc4); acc5 = fmaf(e0, f.y, acc5);
        f = __half22float2(*(const half2*)&p0.w); acc6 = fmaf(e0, f.x, acc6); acc7 = fmaf(e0, f.y, acc7);
    }
    float inv = __fdividef(1.0f, den);
    float4 ba = ((const float4*)b1)[c * 2];
    float4 bb = ((const float4*)b1)[c * 2 + 1];
    float4 o0, o1;
    o0.x = fmaxf(fmaf(acc0, inv, ba.x), 0.f);
    o0.y = fmaxf(fmaf(acc1, inv, ba.y), 0.f);
    o0.z = fmaxf(fmaf(acc2, inv, ba.z), 0.f);
    o0.w = fmaxf(fmaf(acc3, inv, ba.w), 0.f);
    o1.x = fmaxf(fmaf(acc4, inv, bb.x), 0.f);
    o1.y = fmaxf(fmaf(acc5, inv, bb.y), 0.f);
    o1.z = fmaxf(fmaf(acc6, inv, bb.z), 0.f);
    o1.w = fmaxf(fmaf(acc7, inv, bb.w), 0.f);
    float4* op = (float4*)&g_out1[n * H1DIM + c * 8];
    op[0] = o0;
    op[1] = o1;
}

// ---------------- GEMM2 + alpha2: h2 = out1 @ W2 (50000x256 @ 256x32), fp16 h2 ----------------
__global__ void gemm2_kernel(const float* __restrict__ W2,
                             const float* __restrict__ a2s,
                             const float* __restrict__ a2d) {
    __shared__ float xs[8][H1DIM];
    int row0 = blockIdx.x * 8;
    int tid = threadIdx.x;
    const float4* xsrc = (const float4*)&g_out1[row0 * H1DIM];
    float4* xdst = (float4*)&xs[0][0];
#pragma unroll
    for (int i = tid; i < 8 * H1DIM / 4; i += 256) xdst[i] = xsrc[i];
    __syncthreads();
    int r = tid >> 5, c = tid & 31;
    unsigned long long acc = 0ull;
#pragma unroll 8
    for (int k = 0; k < H1DIM; k += 2) {
        float w0 = W2[k * H2DIM + c];
        float w1 = W2[(k + 1) * H2DIM + c];
        unsigned long long wp = pack2(w0, w1);
        unsigned long long xv = *(const unsigned long long*)&xs[r][k];  // LDS.64
        fma2(acc, xv, wp);
    }
    float lo, hi; unpack2(acc, lo, hi);
    float hval = lo + hi;
    int row = row0 + r;
    float partner = __shfl_xor_sync(0xffffffffu, hval, 1);
    if ((c & 1) == 0)
        *(half2*)&g_h2[row * H2DIM + c] = __floats2half2_rn(hval, partner);
    // fused alpha2
    float ps = hval * a2s[c];
    float pd = hval * a2d[c];
#pragma unroll
    for (int off = 16; off; off >>= 1) {
        ps += __shfl_xor_sync(0xffffffffu, ps, off);
        pd += __shfl_xor_sync(0xffffffffu, pd, off);
    }
    if (c == 0) { g_as2[row] = ps; g_ad2[row] = pd; }
}

// ---------------- agg2 + bias + log_softmax + pool: 16 threads/node, inline exp ----------------
__global__ void agg2_lsm_kernel(const float* __restrict__ b2, const int* __restrict__ batch) {
    int gt = blockIdx.x * blockDim.x + threadIdx.x;
    int n = gt >> 4;
    if (n >= NN) return;
    int sub = gt & 15;   // owns cols {2sub, 2sub+1}
    float ad = g_ad2[n];
    int beg = g_off[n], end = g_off[n + 1];
    float ax = 0.f, ay = 0.f, den = 0.f;
    int i = beg;
    for (; i + 2 <= end; i += 2) {
        int s0 = g_csr_src[i], s1 = g_csr_src[i + 1];
        float e0 = __expf(leaky(g_as2[s0] + ad));
        float e1 = __expf(leaky(g_as2[s1] + ad));
        float2 f0 = __half22float2(((const half2*)(g_h2 + s0 * H2DIM))[sub]);
        float2 f1 = __half22float2(((const half2*)(g_h2 + s1 * H2DIM))[sub]);
        den += e0 + e1;
        ax = fmaf(e0, f0.x, fmaf(e1, f1.x, ax));
        ay = fmaf(e0, f0.y, fmaf(e1, f1.y, ay));
    }
    if (i < end) {
        int s0 = g_csr_src[i];
        float e0 = __expf(leaky(g_as2[s0] + ad));
        float2 f0 = __half22float2(((const half2*)(g_h2 + s0 * H2DIM))[sub]);
        den += e0;
        ax = fmaf(e0, f0.x, ax);
        ay = fmaf(e0, f0.y, ay);
    }
    float inv = __fdividef(1.0f, den);
    float v0 = fmaf(ax, inv, b2[sub * 2]);
    float v1 = fmaf(ay, inv, b2[sub * 2 + 1]);
    float mx = fmaxf(v0, v1);
#pragma unroll
    for (int off = 8; off; off >>= 1) mx = fmaxf(mx, __shfl_xor_sync(0xffffffffu, mx, off));
    float s = expf(v0 - mx) + expf(v1 - mx);
#pragma unroll
    for (int off = 8; off; off >>= 1) s += __shfl_xor_sync(0xffffffffu, s, off);
    float lse = mx + logf(s);
    int b = batch[n];
    atomicAdd(&g_pool[b * H2DIM + sub * 2], v0 - lse);
    atomicAdd(&g_pool[b * H2DIM + sub * 2 + 1], v1 - lse);
    if (sub == 0) atomicAdd(&g_cnt[b], 1.0f);
}

// ---------------- final ----------------
__global__ void final_kernel(const float* __restrict__ lin_W, const float* __restrict__ lin_b,
                             float* __restrict__ out) {
    int g = threadIdx.x;
    if (g >= GG) return;
    float inv = 1.0f / fmaxf(g_cnt[g], 1.0f);
    float acc = lin_b[0];
#pragma unroll
    for (int j = 0; j < H2DIM; j++) acc += g_pool[g * H2DIM + j] * inv * lin_W[j];
    out[g] = acc;
}

// ---------------- launcher ----------------
extern "C" void kernel_launch(void* const* d_in, const int* in_sizes, int n_in,
                              void* d_out, int out_size) {
    const float* x      = (const float*)d_in[0];
    const int*   adj    = (const int*)d_in[1];
    const int*   batch  = (const int*)d_in[2];
    const float* W1     = (const float*)d_in[3];
    const float* a1_src = (const float*)d_in[4];
    const float* a1_dst = (const float*)d_in[5];
    const float* b1     = (const float*)d_in[6];
    const float* W2     = (const float*)d_in[7];
    const float* a2_src = (const float*)d_in[8];
    const float* a2_dst = (const float*)d_in[9];
    const float* b2     = (const float*)d_in[10];
    const float* lin_W  = (const float*)d_in[11];
    const float* lin_b  = (const float*)d_in[12];
    float* out = (float*)d_out;

    const int TB = 256;
    int eb = (ET + TB - 1) / TB;

    prep_kernel<<<1, 1024>>>(W1, a1_src, a1_dst);
    hist_kernel<<<eb, TB>>>(adj);
    scan_kernel<<<1, 1024>>>();
    scatter_kernel<<<eb, TB>>>(adj);

    gemm1_kernel<<<NN / 16, TB>>>(x, W1);
    alpha1_kernel<<<(NN * 32 + TB - 1) / TB, TB>>>(x);
    agg1_kernel<<<(NN * 32 + TB - 1) / TB, TB>>>(b1);

    gemm2_kernel<<<NN / 8, TB>>>(W2, a2_src, a2_dst);
    agg2_lsm_kernel<<<(NN * 16 + TB - 1) / TB, TB>>>(b2, batch);

    final_kernel<<<1, 64>>>(lin_W, lin_b, out);
}

// round 9
// speedup vs baseline: 1.7859x; 1.5051x over previous
#include <cuda_runtime.h>
#include <cuda_fp16.h>
#include <math.h>

#define NN 50000
#define EE 800000
#define ET (EE + NN)
#define GG 64
#define F_IN 128
#define H1DIM 256   // HEADS * HID
#define H2DIM 32
#define NEG_SLOPE 0.2f

// ---------------- scratch ----------------
__device__ __align__(16) __half g_h1[NN * H1DIM];     // fp16 layer1 features
__device__ __align__(16) __half g_out1h[NN * H1DIM];  // fp16 layer1 output (gemm2 input)
__device__ __align__(16) float g_as1[NN * 4];
__device__ __align__(16) float g_ad1[NN * 4];
__device__ __align__(16) __half g_h2[NN * H2DIM];     // fp16 layer2 features
__device__ float g_as2[NN];
__device__ float g_ad2[NN];
__device__ float g_pool[GG * H2DIM];
__device__ float g_cnt[GG];
__device__ int g_deg[NN];
__device__ int g_cur[NN];
__device__ int g_off[NN + 1];
__device__ int g_csr_src[ET];
__device__ __align__(16) float g_wsd1[F_IN * 8];      // [f][s0..s3,d0..d3]
__device__ __align__(16) __half g_w1h[F_IN * H1DIM];  // fp16 W1
__device__ __align__(16) __half g_w2h[H1DIM * H2DIM]; // fp16 W2

// ---------------- helpers ----------------
__device__ __forceinline__ float leaky(float e) {
    return (e >= 0.f) ? e : NEG_SLOPE * e;
}
__device__ __forceinline__ unsigned smem_u32(const void* p) {
    return (unsigned)__cvta_generic_to_shared(p);
}
__device__ __forceinline__ void ldsm_x4(unsigned& r0, unsigned& r1, unsigned& r2, unsigned& r3, unsigned a) {
    asm volatile("ldmatrix.sync.aligned.m8n8.x4.shared.b16 {%0,%1,%2,%3},[%4];"
                 : "=r"(r0), "=r"(r1), "=r"(r2), "=r"(r3) : "r"(a));
}
__device__ __forceinline__ void ldsm_x4t(unsigned& r0, unsigned& r1, unsigned& r2, unsigned& r3, unsigned a) {
    asm volatile("ldmatrix.sync.aligned.m8n8.x4.trans.shared.b16 {%0,%1,%2,%3},[%4];"
                 : "=r"(r0), "=r"(r1), "=r"(r2), "=r"(r3) : "r"(a));
}
__device__ __forceinline__ void mma16816(float* d, const unsigned* a, unsigned b0, unsigned b1) {
    asm volatile("mma.sync.aligned.m16n8k16.row.col.f32.f16.f16.f32 "
                 "{%0,%1,%2,%3},{%4,%5,%6,%7},{%8,%9},{%0,%1,%2,%3};"
                 : "+f"(d[0]), "+f"(d[1]), "+f"(d[2]), "+f"(d[3])
                 : "r"(a[0]), "r"(a[1]), "r"(a[2]), "r"(a[3]), "r"(b0), "r"(b1));
}

// ---------------- prep: folded attention vectors, fp16 weights, zero pool ----------------
__global__ void prep_kernel(const float* __restrict__ W1,
                            const float* __restrict__ a1s, const float* __restrict__ a1d,
                            const float* __restrict__ W2) {
    int tid = threadIdx.x;  // 1024
    {
        int f = tid >> 3, o = tid & 7;
        int h = o & 3, sd = o >> 2;
        const float* a = sd ? a1d : a1s;
        float s = 0.f;
#pragma unroll 8
        for (int d = 0; d < 64; d++) s += W1[f * H1DIM + h * 64 + d] * a[h * 64 + d];
        g_wsd1[f * 8 + o] = s;
    }
    for (int j = tid; j < F_IN * H1DIM; j += 1024) g_w1h[j] = __float2half_rn(W1[j]);
    for (int j = tid; j < H1DIM * H2DIM; j += 1024) g_w2h[j] = __float2half_rn(W2[j]);
    for (int j = tid; j < GG * H2DIM; j += 1024) g_pool[j] = 0.f;
    if (tid < GG) g_cnt[tid] = 0.f;
}

// ---------------- CSR build ----------------
__global__ void hist_kernel(const int* __restrict__ adj) {
    int e = blockIdx.x * blockDim.x + threadIdx.x;
    if (e >= ET) return;
    int dst = (e < EE) ? adj[EE + e] : e - EE;
    atomicAdd(&g_deg[dst], 1);
}

__global__ void scan_kernel() {
    __shared__ int warpsum[32];
    int tid = threadIdx.x;
    int lane = tid & 31, wid = tid >> 5;
    int running = 0;
    for (int base = 0; base < NN; base += 1024) {
        int i = base + tid;
        int v = (i < NN) ? g_deg[i] : 0;
        int val = v;
#pragma unroll
        for (int off = 1; off < 32; off <<= 1) {
            int t = __shfl_up_sync(0xffffffffu, val, off);
            if (lane >= off) val += t;
        }
        if (lane == 31) warpsum[wid] = val;
        __syncthreads();
        if (wid == 0) {
            int s = warpsum[lane];
#pragma unroll
            for (int off = 1; off < 32; off <<= 1) {
                int t = __shfl_up_sync(0xffffffffu, s, off);
                if (lane >= off) s += t;
            }
            warpsum[lane] = s;
        }
        __syncthreads();
        int warpbase = (wid == 0) ? 0 : warpsum[wid - 1];
        int excl = running + warpbase + val - v;
        if (i < NN) { g_off[i] = excl; g_cur[i] = excl; }
        running += warpsum[31];
        __syncthreads();
    }
    if (tid == 0) g_off[NN] = running;
}

__global__ void scatter_kernel(const int* __restrict__ adj) {
    int gt = blockIdx.x * blockDim.x + threadIdx.x;
    int stride = gridDim.x * blockDim.x;
    for (int j = gt; j < NN; j += stride) g_deg[j] = 0;
    if (gt >= ET) return;
    int src, dst;
    if (gt < EE) { src = adj[gt]; dst = adj[EE + gt]; }
    else         { src = dst = gt - EE; }
    int p = atomicAdd(&g_cur[dst], 1);
    g_csr_src[p] = src;
}

// ---------------- GEMM1 (HMMA): h1 = x @ W1 (50000x128 @ 128x256) ----------------
// block tile 64x64, 8 warps (4 row x 2 col), warp tile 16x32
__global__ __launch_bounds__(256) void gemm1_mma(const float* __restrict__ x) {
    __shared__ __align__(16) __half As[64][136];   // pad 8: 272B stride
    __shared__ __align__(16) __half Bs[128][72];   // pad 8: 144B stride
    int tid = threadIdx.x;
    int row0 = blockIdx.x * 64;
    int col0 = blockIdx.y * 64;
    // A: 64x128 fp32 -> fp16
    for (int i = tid; i < 64 * 32; i += 256) {
        int r = i >> 5, c4 = i & 31;
        int row = row0 + r;
        float4 v = (row < NN) ? *(const float4*)&x[row * F_IN + c4 * 4]
                              : make_float4(0.f, 0.f, 0.f, 0.f);
        *(half2*)&As[r][c4 * 4] = __floats2half2_rn(v.x, v.y);
        *(half2*)&As[r][c4 * 4 + 2] = __floats2half2_rn(v.z, v.w);
    }
    // B: 128x64 fp16 slice of W1
    for (int i = tid; i < 128 * 8; i += 256) {
        int r = i >> 3, c8 = i & 7;
        *(uint4*)&Bs[r][c8 * 8] = *(const uint4*)&g_w1h[r * H1DIM + col0 + c8 * 8];
    }
    __syncthreads();
    int wid = tid >> 5, lane = tid & 31;
    int rowg = wid >> 1, colg = wid & 1;
    unsigned a[8][4];
#pragma unroll
    for (int ks = 0; ks < 8; ks++) {
        unsigned addr = smem_u32(&As[rowg * 16 + (lane & 15)][ks * 16 + (lane >> 4) * 8]);
        ldsm_x4(a[ks][0], a[ks][1], a[ks][2], a[ks][3], addr);
    }
    float d[4][4];
#pragma unroll
    for (int nt = 0; nt < 4; nt++)
#pragma unroll
        for (int j = 0; j < 4; j++) d[nt][j] = 0.f;
#pragma unroll
    for (int np = 0; np < 2; np++) {
#pragma unroll
        for (int ks = 0; ks < 8; ks++) {
            unsigned b0, b1, b2, b3;
            unsigned addr = smem_u32(&Bs[ks * 16 + (lane & 15)][colg * 32 + np * 16 + (lane >> 4) * 8]);
            ldsm_x4t(b0, b1, b2, b3, addr);
            mma16816(d[np * 2], a[ks], b0, b1);
            mma16816(d[np * 2 + 1], a[ks], b2, b3);
        }
    }
    int g = lane >> 2, t = lane & 3;
    int r_lo = row0 + rowg * 16 + g;
    int r_hi = r_lo + 8;
#pragma unroll
    for (int nt = 0; nt < 4; nt++) {
        int col = col0 + colg * 32 + nt * 8 + 2 * t;
        if (r_lo < NN) *(half2*)&g_h1[r_lo * H1DIM + col] = __floats2half2_rn(d[nt][0], d[nt][1]);
        if (r_hi < NN) *(half2*)&g_h1[r_hi * H1DIM + col] = __floats2half2_rn(d[nt][2], d[nt][3]);
    }
}

// ---------------- alpha1: as1/ad1 = x @ wsd1 (warp per node) ----------------
__global__ void alpha1_kernel(const float* __restrict__ x) {
    int gt = blockIdx.x * blockDim.x + threadIdx.x;
    int n = gt >> 5, lane = gt & 31;
    if (n >= NN) return;
    float4 xv = ((const float4*)x)[n * 32 + lane];
    float a0 = 0, a1 = 0, a2 = 0, a3 = 0, b0 = 0, b1 = 0, b2 = 0, b3 = 0;
    float xj[4] = {xv.x, xv.y, xv.z, xv.w};
#pragma unroll
    for (int j = 0; j < 4; j++) {
        int f = lane * 4 + j;
        float4 wa = *(const float4*)&g_wsd1[f * 8];
        float4 wb = *(const float4*)&g_wsd1[f * 8 + 4];
        a0 = fmaf(xj[j], wa.x, a0); a1 = fmaf(xj[j], wa.y, a1);
        a2 = fmaf(xj[j], wa.z, a2); a3 = fmaf(xj[j], wa.w, a3);
        b0 = fmaf(xj[j], wb.x, b0); b1 = fmaf(xj[j], wb.y, b1);
        b2 = fmaf(xj[j], wb.z, b2); b3 = fmaf(xj[j], wb.w, b3);
    }
#pragma unroll
    for (int off = 16; off; off >>= 1) {
        a0 += __shfl_xor_sync(0xffffffffu, a0, off);
        a1 += __shfl_xor_sync(0xffffffffu, a1, off);
        a2 += __shfl_xor_sync(0xffffffffu, a2, off);
        a3 += __shfl_xor_sync(0xffffffffu, a3, off);
        b0 += __shfl_xor_sync(0xffffffffu, b0, off);
        b1 += __shfl_xor_sync(0xffffffffu, b1, off);
        b2 += __shfl_xor_sync(0xffffffffu, b2, off);
        b3 += __shfl_xor_sync(0xffffffffu, b3, off);
    }
    if (lane == 0) {
        *(float4*)&g_as1[n * 4] = make_float4(a0, a1, a2, a3);
        *(float4*)&g_ad1[n * 4] = make_float4(b0, b1, b2, b3);
    }
}

// ---------------- agg1: 32 threads/node, inline exp, fp16 gathers, fp16 out ----------------
__global__ void agg1_kernel(const float* __restrict__ b1) {
    int gt = blockIdx.x * blockDim.x + threadIdx.x;
    int n = gt >> 5;
    if (n >= NN) return;
    int c = gt & 31;
    int head = c >> 3;
    float adh = g_ad1[n * 4 + head];
    int beg = g_off[n], end = g_off[n + 1];
    float acc0 = 0, acc1 = 0, acc2 = 0, acc3 = 0, acc4 = 0, acc5 = 0, acc6 = 0, acc7 = 0;
    float den = 0.f;
    int i = beg;
    for (; i + 2 <= end; i += 2) {
        int s0 = g_csr_src[i], s1 = g_csr_src[i + 1];
        float e0 = __expf(leaky(g_as1[s0 * 4 + head] + adh));
        float e1 = __expf(leaky(g_as1[s1 * 4 + head] + adh));
        uint4 p0 = ((const uint4*)(g_h1 + s0 * H1DIM))[c];
        uint4 p1 = ((const uint4*)(g_h1 + s1 * H1DIM))[c];
        den += e0 + e1;
        float2 f;
        f = __half22float2(*(const half2*)&p0.x); acc0 = fmaf(e0, f.x, acc0); acc1 = fmaf(e0, f.y, acc1);
        f = __half22float2(*(const half2*)&p0.y); acc2 = fmaf(e0, f.x, acc2); acc3 = fmaf(e0, f.y, acc3);
        f = __half22float2(*(const half2*)&p0.z); acc4 = fmaf(e0, f.x, acc4); acc5 = fmaf(e0, f.y, acc5);
        f = __half22float2(*(const half2*)&p0.w); acc6 = fmaf(e0, f.x, acc6); acc7 = fmaf(e0, f.y, acc7);
        f = __half22float2(*(const half2*)&p1.x); acc0 = fmaf(e1, f.x, acc0); acc1 = fmaf(e1, f.y, acc1);
        f = __half22float2(*(const half2*)&p1.y); acc2 = fmaf(e1, f.x, acc2); acc3 = fmaf(e1, f.y, acc3);
        f = __half22float2(*(const half2*)&p1.z); acc4 = fmaf(e1, f.x, acc4); acc5 = fmaf(e1, f.y, acc5);
        f = __half22float2(*(const half2*)&p1.w); acc6 = fmaf(e1, f.x, acc6); acc7 = fmaf(e1, f.y, acc7);
    }
    if (i < end) {
        int s0 = g_csr_src[i];
        float e0 = __expf(leaky(g_as1[s0 * 4 + head] + adh));
        uint4 p0 = ((const uint4*)(g_h1 + s0 * H1DIM))[c];
        den += e0;
        float2 f;
        f = __half22float2(*(const half2*)&p0.x); acc0 = fmaf(e0, f.x, acc0); acc1 = fmaf(e0, f.y, acc1);
        f = __half22float2(*(const half2*)&p0.y); acc2 = fmaf(e0, f.x, acc2); acc3 = fmaf(e0, f.y, acc3);
        f = __half22float2(*(const half2*)&p0.z); acc4 = fmaf(e0, f.x, acc4); acc5 = fmaf(e0, f.y, acc5);
        f = __half22float2(*(const half2*)&p0.w); acc6 = fmaf(e0, f.x, acc6); acc7 = fmaf(e0, f.y, acc7);
    }
    float inv = __fdividef(1.0f, den);
    float4 ba = ((const float4*)b1)[c * 2];
    float4 bb = ((const float4*)b1)[c * 2 + 1];
    half2 h0 = __floats2half2_rn(fmaxf(fmaf(acc0, inv, ba.x), 0.f), fmaxf(fmaf(acc1, inv, ba.y), 0.f));
    half2 h1p = __floats2half2_rn(fmaxf(fmaf(acc2, inv, ba.z), 0.f), fmaxf(fmaf(acc3, inv, ba.w), 0.f));
    half2 h2p = __floats2half2_rn(fmaxf(fmaf(acc4, inv, bb.x), 0.f), fmaxf(fmaf(acc5, inv, bb.y), 0.f));
    half2 h3p = __floats2half2_rn(fmaxf(fmaf(acc6, inv, bb.z), 0.f), fmaxf(fmaf(acc7, inv, bb.w), 0.f));
    uint4 pk;
    pk.x = *(unsigned*)&h0; pk.y = *(unsigned*)&h1p; pk.z = *(unsigned*)&h2p; pk.w = *(unsigned*)&h3p;
    ((uint4*)(g_out1h + n * H1DIM))[c] = pk;
}

// ---------------- GEMM2 (HMMA) + alpha2: h2 = out1h @ W2 (50000x256 @ 256x32) ----------------
// block tile 128 rows, 8 warps x 16 rows; K=256 in 2 stages of 128
__global__ __launch_bounds__(256) void gemm2_mma(const float* __restrict__ a2s,
                                                 const float* __restrict__ a2d) {
    __shared__ __align__(16) __half As[128][136];
    __shared__ __align__(16) __half Bs[128][40];
    int tid = threadIdx.x;
    int row0 = blockIdx.x * 128;
    int wid = tid >> 5, lane = tid & 31;
    float d[4][4];
#pragma unroll
    for (int nt = 0; nt < 4; nt++)
#pragma unroll
        for (int j = 0; j < 4; j++) d[nt][j] = 0.f;
    for (int st = 0; st < 2; st++) {
        for (int i = tid; i < 128 * 16; i += 256) {
            int r = i >> 4, c8 = i & 15;
            int row = row0 + r;
            uint4 v = (row < NN) ? *(const uint4*)&g_out1h[row * H1DIM + st * 128 + c8 * 8]
                                 : make_uint4(0u, 0u, 0u, 0u);
            *(uint4*)&As[r][c8 * 8] = v;
        }
        for (int i = tid; i < 128 * 4; i += 256) {
            int r = i >> 2, c8 = i & 3;
            *(uint4*)&Bs[r][c8 * 8] = *(const uint4*)&g_w2h[(st * 128 + r) * H2DIM + c8 * 8];
        }
        __syncthreads();
#pragma unroll
        for (int ks = 0; ks < 8; ks++) {
            unsigned a[4];
            unsigned aaddr = smem_u32(&As[wid * 16 + (lane & 15)][ks * 16 + (lane >> 4) * 8]);
            ldsm_x4(a[0], a[1], a[2], a[3], aaddr);
#pragma unroll
            for (int np = 0; np < 2; np++) {
                unsigned b0, b1, b2, b3;
                unsigned baddr = smem_u32(&Bs[ks * 16 + (lane & 15)][np * 16 + (lane >> 4) * 8]);
                ldsm_x4t(b0, b1, b2, b3, baddr);
                mma16816(d[np * 2], a, b0, b1);
                mma16816(d[np * 2 + 1], a, b2, b3);
            }
        }
        __syncthreads();
    }
    int g = lane >> 2, t = lane & 3;
    int r_lo = row0 + wid * 16 + g;
    int r_hi = r_lo + 8;
    float ps_lo = 0, pd_lo = 0, ps_hi = 0, pd_hi = 0;
#pragma unroll
    for (int nt = 0; nt < 4; nt++) {
        int col = nt * 8 + 2 * t;
        float s0 = a2s[col], s1 = a2s[col + 1];
        float t0 = a2d[col], t1 = a2d[col + 1];
        if (r_lo < NN) *(half2*)&g_h2[r_lo * H2DIM + col] = __floats2half2_rn(d[nt][0], d[nt][1]);
        if (r_hi < NN) *(half2*)&g_h2[r_hi * H2DIM + col] = __floats2half2_rn(d[nt][2], d[nt][3]);
        ps_lo += d[nt][0] * s0 + d[nt][1] * s1;
        pd_lo += d[nt][0] * t0 + d[nt][1] * t1;
        ps_hi += d[nt][2] * s0 + d[nt][3] * s1;
        pd_hi += d[nt][2] * t0 + d[nt][3] * t1;
    }
#pragma unroll
    for (int off = 1; off <= 2; off <<= 1) {
        ps_lo += __shfl_xor_sync(0xffffffffu, ps_lo, off);
        pd_lo += __shfl_xor_sync(0xffffffffu, pd_lo, off);
        ps_hi += __shfl_xor_sync(0xffffffffu, ps_hi, off);
        pd_hi += __shfl_xor_sync(0xffffffffu, pd_hi, off);
    }
    if (t == 0) {
        if (r_lo < NN) { g_as2[r_lo] = ps_lo; g_ad2[r_lo] = pd_lo; }
        if (r_hi < NN) { g_as2[r_hi] = ps_hi; g_ad2[r_hi] = pd_hi; }
    }
}

// ---------------- agg2 + bias + log_softmax + pool: 16 threads/node, inline exp ----------------
__global__ void agg2_lsm_kernel(const float* __restrict__ b2, const int* __restrict__ batch) {
    int gt = blockIdx.x * blockDim.x + threadIdx.x;
    int n = gt >> 4;
    if (n >= NN) return;
    int sub = gt & 15;
    float ad = g_ad2[n];
    int beg = g_off[n], end = g_off[n + 1];
    float ax = 0.f, ay = 0.f, den = 0.f;
    int i = beg;
    for (; i + 2 <= end; i += 2) {
        int s0 = g_csr_src[i], s1 = g_csr_src[i + 1];
        float e0 = __expf(leaky(g_as2[s0] + ad));
        float e1 = __expf(leaky(g_as2[s1] + ad));
        float2 f0 = __half22float2(((const half2*)(g_h2 + s0 * H2DIM))[sub]);
        float2 f1 = __half22float2(((const half2*)(g_h2 + s1 * H2DIM))[sub]);
        den += e0 + e1;
        ax = fmaf(e0, f0.x, fmaf(e1, f1.x, ax));
        ay = fmaf(e0, f0.y, fmaf(e1, f1.y, ay));
    }
    if (i < end) {
        int s0 = g_csr_src[i];
        float e0 = __expf(leaky(g_as2[s0] + ad));
        float2 f0 = __half22float2(((const half2*)(g_h2 + s0 * H2DIM))[sub]);
        den += e0;
        ax = fmaf(e0, f0.x, ax);
        ay = fmaf(e0, f0.y, ay);
    }
    float inv = __fdividef(1.0f, den);
    float v0 = fmaf(ax, inv, b2[sub * 2]);
    float v1 = fmaf(ay, inv, b2[sub * 2 + 1]);
    float mx = fmaxf(v0, v1);
#pragma unroll
    for (int off = 8; off; off >>= 1) mx = fmaxf(mx, __shfl_xor_sync(0xffffffffu, mx, off));
    float s = expf(v0 - mx) + expf(v1 - mx);
#pragma unroll
    for (int off = 8; off; off >>= 1) s += __shfl_xor_sync(0xffffffffu, s, off);
    float lse = mx + logf(s);
    int b = batch[n];
    atomicAdd(&g_pool[b * H2DIM + sub * 2], v0 - lse);
    atomicAdd(&g_pool[b * H2DIM + sub * 2 + 1], v1 - lse);
    if (sub == 0) atomicAdd(&g_cnt[b], 1.0f);
}

// ---------------- final ----------------
__global__ void final_kernel(const float* __restrict__ lin_W, const float* __restrict__ lin_b,
                             float* __restrict__ out) {
    int g = threadIdx.x;
    if (g >= GG) return;
    float inv = 1.0f / fmaxf(g_cnt[g], 1.0f);
    float acc = lin_b[0];
#pragma unroll
    for (int j = 0; j < H2DIM; j++) acc += g_pool[g * H2DIM + j] * inv * lin_W[j];
    out[g] = acc;
}

// ---------------- launcher ----------------
extern "C" void kernel_launch(void* const* d_in, const int* in_sizes, int n_in,
                              void* d_out, int out_size) {
    const float* x      = (const float*)d_in[0];
    const int*   adj    = (const int*)d_in[1];
    const int*   batch  = (const int*)d_in[2];
    const float* W1     = (const float*)d_in[3];
    const float* a1_src = (const float*)d_in[4];
    const float* a1_dst = (const float*)d_in[5];
    const float* b1     = (const float*)d_in[6];
    const float* W2     = (const float*)d_in[7];
    const float* a2_src = (const float*)d_in[8];
    const float* a2_dst = (const float*)d_in[9];
    const float* b2     = (const float*)d_in[10];
    const float* lin_W  = (const float*)d_in[11];
    const float* lin_b  = (const float*)d_in[12];
    float* out = (float*)d_out;

    const int TB = 256;
    int eb = (ET + TB - 1) / TB;

    prep_kernel<<<1, 1024>>>(W1, a1_src, a1_dst, W2);
    hist_kernel<<<eb, TB>>>(adj);
    scan_kernel<<<1, 1024>>>();
    scatter_kernel<<<eb, TB>>>(adj);

    dim3 g1((NN + 63) / 64, H1DIM / 64);
    gemm1_mma<<<g1, TB>>>(x);
    alpha1_kernel<<<(NN * 32 + TB - 1) / TB, TB>>>(x);
    agg1_kernel<<<(NN * 32 + TB - 1) / TB, TB>>>(b1);

    gemm2_mma<<<(NN + 127) / 128, TB>>>(a2_src, a2_dst);
    agg2_lsm_kernel<<<(NN * 16 + TB - 1) / TB, TB>>>(b2, batch);

    final_kernel<<<1, 64>>>(lin_W, lin_b, out);
}

// round 10
// speedup vs baseline: 1.9479x; 1.0907x over previous
#include <cuda_runtime.h>
#include <cuda_fp16.h>
#include <math.h>

#define NN 50000
#define EE 800000
#define ET (EE + NN)
#define GG 64
#define F_IN 128
#define H1DIM 256   // HEADS * HID
#define H2DIM 32
#define NEG_SLOPE 0.2f
#define EB 3321                 // ceil(ET/256)
#define G1B 3128                // gemm1 blocks: 782 row-blocks x 4 col-blocks
#define A1B 6250                // alpha1 blocks: NN*32/256

// ---------------- scratch ----------------
__device__ __align__(16) __half g_h1[NN * H1DIM];     // fp16 layer1 features
__device__ __align__(16) __half g_out1h[NN * H1DIM];  // fp16 layer1 output (gemm2 input)
__device__ __align__(16) float g_as1[NN * 4];
__device__ __align__(16) float g_ad1[NN * 4];
__device__ __align__(16) __half g_h2[NN * H2DIM];     // fp16 layer2 features
__device__ float g_as2[NN];
__device__ float g_ad2[NN];
__device__ float g_pool[GG * H2DIM];
__device__ float g_cnt[GG];
__device__ int g_deg[NN];
__device__ int g_cur[NN];
__device__ int g_off[NN + 1];
__device__ int g_csr_src[ET];
__device__ __align__(16) float g_wsd1[F_IN * 8];      // [f][s0..s3,d0..d3]
__device__ __align__(16) __half g_w1h[F_IN * H1DIM];  // fp16 W1
__device__ __align__(16) __half g_w2h[H1DIM * H2DIM]; // fp16 W2

// ---------------- helpers ----------------
__device__ __forceinline__ float leaky(float e) {
    return (e >= 0.f) ? e : NEG_SLOPE * e;
}
__device__ __forceinline__ unsigned smem_u32(const void* p) {
    return (unsigned)__cvta_generic_to_shared(p);
}
__device__ __forceinline__ void ldsm_x4(unsigned& r0, unsigned& r1, unsigned& r2, unsigned& r3, unsigned a) {
    asm volatile("ldmatrix.sync.aligned.m8n8.x4.shared.b16 {%0,%1,%2,%3},[%4];"
                 : "=r"(r0), "=r"(r1), "=r"(r2), "=r"(r3) : "r"(a));
}
__device__ __forceinline__ void ldsm_x4t(unsigned& r0, unsigned& r1, unsigned& r2, unsigned& r3, unsigned a) {
    asm volatile("ldmatrix.sync.aligned.m8n8.x4.trans.shared.b16 {%0,%1,%2,%3},[%4];"
                 : "=r"(r0), "=r"(r1), "=r"(r2), "=r"(r3) : "r"(a));
}
__device__ __forceinline__ void mma16816(float* d, const unsigned* a, unsigned b0, unsigned b1) {
    asm volatile("mma.sync.aligned.m16n8k16.row.col.f32.f16.f16.f32 "
                 "{%0,%1,%2,%3},{%4,%5,%6,%7},{%8,%9},{%0,%1,%2,%3};"
                 : "+f"(d[0]), "+f"(d[1]), "+f"(d[2]), "+f"(d[3])
                 : "r"(a[0]), "r"(a[1]), "r"(a[2]), "r"(a[3]), "r"(b0), "r"(b1));
}

// ---------------- K1: prep (4 blocks) + hist (EB blocks) fused ----------------
__global__ void prep_hist_kernel(const int* __restrict__ adj,
                                 const float* __restrict__ W1,
                                 const float* __restrict__ a1s, const float* __restrict__ a1d,
                                 const float* __restrict__ W2) {
    int bx = blockIdx.x;
    int tid = threadIdx.x;
    if (bx < EB) {
        int e = bx * 256 + tid;
        if (e >= ET) return;
        int dst = (e < EE) ? adj[EE + e] : e - EE;
        atomicAdd(&g_deg[dst], 1);
    } else {
        int pt = (bx - EB) * 256 + tid;  // 0..1023
        {
            int f = pt >> 3, o = pt & 7;
            int h = o & 3, sd = o >> 2;
            const float* a = sd ? a1d : a1s;
            float s = 0.f;
#pragma unroll 8
            for (int d = 0; d < 64; d++) s += W1[f * H1DIM + h * 64 + d] * a[h * 64 + d];
            g_wsd1[f * 8 + o] = s;
        }
        for (int j = pt; j < F_IN * H1DIM; j += 1024) g_w1h[j] = __float2half_rn(W1[j]);
        for (int j = pt; j < H1DIM * H2DIM; j += 1024) g_w2h[j] = __float2half_rn(W2[j]);
        for (int j = pt; j < GG * H2DIM; j += 1024) g_pool[j] = 0.f;
        if (pt < GG) g_cnt[pt] = 0.f;
    }
}

// ---------------- K2: coalesced block scan ----------------
__global__ void scan_kernel() {
    __shared__ int warpsum[32];
    int tid = threadIdx.x;
    int lane = tid & 31, wid = tid >> 5;
    int running = 0;
    for (int base = 0; base < NN; base += 1024) {
        int i = base + tid;
        int v = (i < NN) ? g_deg[i] : 0;
        int val = v;
#pragma unroll
        for (int off = 1; off < 32; off <<= 1) {
            int t = __shfl_up_sync(0xffffffffu, val, off);
            if (lane >= off) val += t;
        }
        if (lane == 31) warpsum[wid] = val;
        __syncthreads();
        if (wid == 0) {
            int s = warpsum[lane];
#pragma unroll
            for (int off = 1; off < 32; off <<= 1) {
                int t = __shfl_up_sync(0xffffffffu, s, off);
                if (lane >= off) s += t;
            }
            warpsum[lane] = s;
        }
        __syncthreads();
        int warpbase = (wid == 0) ? 0 : warpsum[wid - 1];
        int excl = running + warpbase + val - v;
        if (i < NN) { g_off[i] = excl; g_cur[i] = excl; }
        running += warpsum[31];
        __syncthreads();
    }
    if (tid == 0) g_off[NN] = running;
}

// ---------------- K3 bodies ----------------
__device__ __forceinline__ void scatter_body(int base, const int* __restrict__ adj) {
    int tid = threadIdx.x;
    int gt = base * 256 + tid;
    const int STR = EB * 256;
    for (int j = gt; j < NN; j += STR) g_deg[j] = 0;   // reset for next replay
    if (gt >= ET) return;
    int src, dst;
    if (gt < EE) { src = adj[gt]; dst = adj[EE + gt]; }
    else         { src = dst = gt - EE; }
    int p = atomicAdd(&g_cur[dst], 1);
    g_csr_src[p] = src;
}

__device__ __forceinline__ void alpha1_body(int aid, const float* __restrict__ x) {
    int gt = aid * 256 + threadIdx.x;
    int n = gt >> 5, lane = gt & 31;
    if (n >= NN) return;
    float4 xv = ((const float4*)x)[n * 32 + lane];
    float a0 = 0, a1 = 0, a2 = 0, a3 = 0, b0 = 0, b1 = 0, b2 = 0, b3 = 0;
    float xj[4] = {xv.x, xv.y, xv.z, xv.w};
#pragma unroll
    for (int j = 0; j < 4; j++) {
        int f = lane * 4 + j;
        float4 wa = *(const float4*)&g_wsd1[f * 8];
        float4 wb = *(const float4*)&g_wsd1[f * 8 + 4];
        a0 = fmaf(xj[j], wa.x, a0); a1 = fmaf(xj[j], wa.y, a1);
        a2 = fmaf(xj[j], wa.z, a2); a3 = fmaf(xj[j], wa.w, a3);
        b0 = fmaf(xj[j], wb.x, b0); b1 = fmaf(xj[j], wb.y, b1);
        b2 = fmaf(xj[j], wb.z, b2); b3 = fmaf(xj[j], wb.w, b3);
    }
#pragma unroll
    for (int off = 16; off; off >>= 1) {
        a0 += __shfl_xor_sync(0xffffffffu, a0, off);
        a1 += __shfl_xor_sync(0xffffffffu, a1, off);
        a2 += __shfl_xor_sync(0xffffffffu, a2, off);
        a3 += __shfl_xor_sync(0xffffffffu, a3, off);
        b0 += __shfl_xor_sync(0xffffffffu, b0, off);
        b1 += __shfl_xor_sync(0xffffffffu, b1, off);
        b2 += __shfl_xor_sync(0xffffffffu, b2, off);
        b3 += __shfl_xor_sync(0xffffffffu, b3, off);
    }
    if (lane == 0) {
        *(float4*)&g_as1[n * 4] = make_float4(a0, a1, a2, a3);
        *(float4*)&g_ad1[n * 4] = make_float4(b0, b1, b2, b3);
    }
}

// ---------------- K3: scatter + gemm1(HMMA) + alpha1, striped roles ----------------
__global__ __launch_bounds__(256) void mid_kernel(const int* __restrict__ adj,
                                                  const float* __restrict__ x) {
    __shared__ __align__(16) __half As[64][136];
    __shared__ __align__(16) __half Bs[128][72];
    int m = blockIdx.x & 3, base = blockIdx.x >> 2;
    if (m == 2) { if (base < EB) scatter_body(base, adj); return; }
    if (m & 1)  { int aid = base * 2 + (m == 3); if (aid < A1B) alpha1_body(aid, x); return; }
    if (base >= G1B) return;
    // gemm1: row-block = base>>2, col-block = base&3
    int tid = threadIdx.x;
    int row0 = (base >> 2) * 64;
    int col0 = (base & 3) * 64;
    for (int i = tid; i < 64 * 32; i += 256) {
        int r = i >> 5, c4 = i & 31;
        int row = row0 + r;
        float4 v = (row < NN) ? *(const float4*)&x[row * F_IN + c4 * 4]
                              : make_float4(0.f, 0.f, 0.f, 0.f);
        *(half2*)&As[r][c4 * 4] = __floats2half2_rn(v.x, v.y);
        *(half2*)&As[r][c4 * 4 + 2] = __floats2half2_rn(v.z, v.w);
    }
    for (int i = tid; i < 128 * 8; i += 256) {
        int r = i >> 3, c8 = i & 7;
        *(uint4*)&Bs[r][c8 * 8] = *(const uint4*)&g_w1h[r * H1DIM + col0 + c8 * 8];
    }
    __syncthreads();
    int wid = tid >> 5, lane = tid & 31;
    int rowg = wid >> 1, colg = wid & 1;
    unsigned a[8][4];
#pragma unroll
    for (int ks = 0; ks < 8; ks++) {
        unsigned addr = smem_u32(&As[rowg * 16 + (lane & 15)][ks * 16 + (lane >> 4) * 8]);
        ldsm_x4(a[ks][0], a[ks][1], a[ks][2], a[ks][3], addr);
    }
    float d[4][4];
#pragma unroll
    for (int nt = 0; nt < 4; nt++)
#pragma unroll
        for (int j = 0; j < 4; j++) d[nt][j] = 0.f;
#pragma unroll
    for (int np = 0; np < 2; np++) {
#pragma unroll
        for (int ks = 0; ks < 8; ks++) {
            unsigned b0, b1, b2, b3;
            unsigned addr = smem_u32(&Bs[ks * 16 + (lane & 15)][colg * 32 + np * 16 + (lane >> 4) * 8]);
            ldsm_x4t(b0, b1, b2, b3, addr);
            mma16816(d[np * 2], a[ks], b0, b1);
            mma16816(d[np * 2 + 1], a[ks], b2, b3);
        }
    }
    int g = lane >> 2, t = lane & 3;
    int r_lo = row0 + rowg * 16 + g;
    int r_hi = r_lo + 8;
#pragma unroll
    for (int nt = 0; nt < 4; nt++) {
        int col = col0 + colg * 32 + nt * 8 + 2 * t;
        if (r_lo < NN) *(half2*)&g_h1[r_lo * H1DIM + col] = __floats2half2_rn(d[nt][0], d[nt][1]);
        if (r_hi < NN) *(half2*)&g_h1[r_hi * H1DIM + col] = __floats2half2_rn(d[nt][2], d[nt][3]);
    }
}

// ---------------- agg1: 32 threads/node, inline exp, unroll-4 gathers ----------------
__device__ __forceinline__ void acc8(float* acc, float e, const uint4& p) {
    float2 f;
    f = __half22float2(*(const half2*)&p.x); acc[0] = fmaf(e, f.x, acc[0]); acc[1] = fmaf(e, f.y, acc[1]);
    f = __half22float2(*(const half2*)&p.y); acc[2] = fmaf(e, f.x, acc[2]); acc[3] = fmaf(e, f.y, acc[3]);
    f = __half22float2(*(const half2*)&p.z); acc[4] = fmaf(e, f.x, acc[4]); acc[5] = fmaf(e, f.y, acc[5]);
    f = __half22float2(*(const half2*)&p.w); acc[6] = fmaf(e, f.x, acc[6]); acc[7] = fmaf(e, f.y, acc[7]);
}

__global__ void agg1_kernel(const float* __restrict__ b1) {
    int gt = blockIdx.x * blockDim.x + threadIdx.x;
    int n = gt >> 5;
    if (n >= NN) return;
    int c = gt & 31;
    int head = c >> 3;
    float adh = g_ad1[n * 4 + head];
    int beg = g_off[n], end = g_off[n + 1];
    float acc[8] = {0, 0, 0, 0, 0, 0, 0, 0};
    float den = 0.f;
    int i = beg;
    for (; i + 4 <= end; i += 4) {
        int s0 = g_csr_src[i], s1 = g_csr_src[i + 1];
        int s2 = g_csr_src[i + 2], s3 = g_csr_src[i + 3];
        float e0 = __expf(leaky(g_as1[s0 * 4 + head] + adh));
        float e1 = __expf(leaky(g_as1[s1 * 4 + head] + adh));
        float e2 = __expf(leaky(g_as1[s2 * 4 + head] + adh));
        float e3 = __expf(leaky(g_as1[s3 * 4 + head] + adh));
        uint4 p0 = ((const uint4*)(g_h1 + s0 * H1DIM))[c];
        uint4 p1 = ((const uint4*)(g_h1 + s1 * H1DIM))[c];
        uint4 p2 = ((const uint4*)(g_h1 + s2 * H1DIM))[c];
        uint4 p3 = ((const uint4*)(g_h1 + s3 * H1DIM))[c];
        den += (e0 + e1) + (e2 + e3);
        acc8(acc, e0, p0); acc8(acc, e1, p1); acc8(acc, e2, p2); acc8(acc, e3, p3);
    }
    for (; i < end; i++) {
        int s0 = g_csr_src[i];
        float e0 = __expf(leaky(g_as1[s0 * 4 + head] + adh));
        uint4 p0 = ((const uint4*)(g_h1 + s0 * H1DIM))[c];
        den += e0;
        acc8(acc, e0, p0);
    }
    float inv = __fdividef(1.0f, den);
    float4 ba = ((const float4*)b1)[c * 2];
    float4 bb = ((const float4*)b1)[c * 2 + 1];
    half2 h0 = __floats2half2_rn(fmaxf(fmaf(acc[0], inv, ba.x), 0.f), fmaxf(fmaf(acc[1], inv, ba.y), 0.f));
    half2 h1p = __floats2half2_rn(fmaxf(fmaf(acc[2], inv, ba.z), 0.f), fmaxf(fmaf(acc[3], inv, ba.w), 0.f));
    half2 h2p = __floats2half2_rn(fmaxf(fmaf(acc[4], inv, bb.x), 0.f), fmaxf(fmaf(acc[5], inv, bb.y), 0.f));
    half2 h3p = __floats2half2_rn(fmaxf(fmaf(acc[6], inv, bb.z), 0.f), fmaxf(fmaf(acc[7], inv, bb.w), 0.f));
    uint4 pk;
    pk.x = *(unsigned*)&h0; pk.y = *(unsigned*)&h1p; pk.z = *(unsigned*)&h2p; pk.w = *(unsigned*)&h3p;
    ((uint4*)(g_out1h + n * H1DIM))[c] = pk;
}

// ---------------- GEMM2 (HMMA) + alpha2 ----------------
__global__ __launch_bounds__(256) void gemm2_mma(const float* __restrict__ a2s,
                                                 const float* __restrict__ a2d) {
    __shared__ __align__(16) __half As[128][136];
    __shared__ __align__(16) __half Bs[128][40];
    int tid = threadIdx.x;
    int row0 = blockIdx.x * 128;
    int wid = tid >> 5, lane = tid & 31;
    float d[4][4];
#pragma unroll
    for (int nt = 0; nt < 4; nt++)
#pragma unroll
        for (int j = 0; j < 4; j++) d[nt][j] = 0.f;
    for (int st = 0; st < 2; st++) {
        for (int i = tid; i < 128 * 16; i += 256) {
            int r = i >> 4, c8 = i & 15;
            int row = row0 + r;
            uint4 v = (row < NN) ? *(const uint4*)&g_out1h[row * H1DIM + st * 128 + c8 * 8]
                                 : make_uint4(0u, 0u, 0u, 0u);
            *(uint4*)&As[r][c8 * 8] = v;
        }
        for (int i = tid; i < 128 * 4; i += 256) {
            int r = i >> 2, c8 = i & 3;
            *(uint4*)&Bs[r][c8 * 8] = *(const uint4*)&g_w2h[(st * 128 + r) * H2DIM + c8 * 8];
        }
        __syncthreads();
#pragma unroll
        for (int ks = 0; ks < 8; ks++) {
            unsigned a[4];
            unsigned aaddr = smem_u32(&As[wid * 16 + (lane & 15)][ks * 16 + (lane >> 4) * 8]);
            ldsm_x4(a[0], a[1], a[2], a[3], aaddr);
#pragma unroll
            for (int np = 0; np < 2; np++) {
                unsigned b0, b1, b2, b3;
                unsigned baddr = smem_u32(&Bs[ks * 16 + (lane & 15)][np * 16 + (lane >> 4) * 8]);
                ldsm_x4t(b0, b1, b2, b3, baddr);
                mma16816(d[np * 2], a, b0, b1);
                mma16816(d[np * 2 + 1], a, b2, b3);
            }
        }
        __syncthreads();
    }
    int g = lane >> 2, t = lane & 3;
    int r_lo = row0 + wid * 16 + g;
    int r_hi = r_lo + 8;
    float ps_lo = 0, pd_lo = 0, ps_hi = 0, pd_hi = 0;
#pragma unroll
    for (int nt = 0; nt < 4; nt++) {
        int col = nt * 8 + 2 * t;
        float s0 = a2s[col], s1 = a2s[col + 1];
        float t0 = a2d[col], t1 = a2d[col + 1];
        if (r_lo < NN) *(half2*)&g_h2[r_lo * H2DIM + col] = __floats2half2_rn(d[nt][0], d[nt][1]);
        if (r_hi < NN) *(half2*)&g_h2[r_hi * H2DIM + col] = __floats2half2_rn(d[nt][2], d[nt][3]);
        ps_lo += d[nt][0] * s0 + d[nt][1] * s1;
        pd_lo += d[nt][0] * t0 + d[nt][1] * t1;
        ps_hi += d[nt][2] * s0 + d[nt][3] * s1;
        pd_hi += d[nt][2] * t0 + d[nt][3] * t1;
    }
#pragma unroll
    for (int off = 1; off <= 2; off <<= 1) {
        ps_lo += __shfl_xor_sync(0xffffffffu, ps_lo, off);
        pd_lo += __shfl_xor_sync(0xffffffffu, pd_lo, off);
        ps_hi += __shfl_xor_sync(0xffffffffu, ps_hi, off);
        pd_hi += __shfl_xor_sync(0xffffffffu, pd_hi, off);
    }
    if (t == 0) {
        if (r_lo < NN) { g_as2[r_lo] = ps_lo; g_ad2[r_lo] = pd_lo; }
        if (r_hi < NN) { g_as2[r_hi] = ps_hi; g_ad2[r_hi] = pd_hi; }
    }
}

// ---------------- agg2 + bias + log_softmax + pool ----------------
__global__ void agg2_lsm_kernel(const float* __restrict__ b2, const int* __restrict__ batch) {
    int gt = blockIdx.x * blockDim.x + threadIdx.x;
    int n = gt >> 4;
    if (n >= NN) return;
    int sub = gt & 15;
    float ad = g_ad2[n];
    int beg = g_off[n], end = g_off[n + 1];
    float ax = 0.f, ay = 0.f, den = 0.f;
    int i = beg;
    for (; i + 4 <= end; i += 4) {
        int s0 = g_csr_src[i], s1 = g_csr_src[i + 1];
        int s2 = g_csr_src[i + 2], s3 = g_csr_src[i + 3];
        float e0 = __expf(leaky(g_as2[s0] + ad));
        float e1 = __expf(leaky(g_as2[s1] + ad));
        float e2 = __expf(leaky(g_as2[s2] + ad));
        float e3 = __expf(leaky(g_as2[s3] + ad));
        float2 f0 = __half22float2(((const half2*)(g_h2 + s0 * H2DIM))[sub]);
        float2 f1 = __half22float2(((const half2*)(g_h2 + s1 * H2DIM))[sub]);
        float2 f2 = __half22float2(((const half2*)(g_h2 + s2 * H2DIM))[sub]);
        float2 f3 = __half22float2(((const half2*)(g_h2 + s3 * H2DIM))[sub]);
        den += (e0 + e1) + (e2 + e3);
        ax = fmaf(e0, f0.x, fmaf(e1, f1.x, fmaf(e2, f2.x, fmaf(e3, f3.x, ax))));
        ay = fmaf(e0, f0.y, fmaf(e1, f1.y, fmaf(e2, f2.y, fmaf(e3, f3.y, ay))));
    }
    for (; i < end; i++) {
        int s0 = g_csr_src[i];
        float e0 = __expf(leaky(g_as2[s0] + ad));
        float2 f0 = __half22float2(((const half2*)(g_h2 + s0 * H2DIM))[sub]);
        den += e0;
        ax = fmaf(e0, f0.x, ax);
        ay = fmaf(e0, f0.y, ay);
    }
    float inv = __fdividef(1.0f, den);
    float v0 = fmaf(ax, inv, b2[sub * 2]);
    float v1 = fmaf(ay, inv, b2[sub * 2 + 1]);
    float mx = fmaxf(v0, v1);
#pragma unroll
    for (int off = 8; off; off >>= 1) mx = fmaxf(mx, __shfl_xor_sync(0xffffffffu, mx, off));
    float s = expf(v0 - mx) + expf(v1 - mx);
#pragma unroll
    for (int off = 8; off; off >>= 1) s += __shfl_xor_sync(0xffffffffu, s, off);
    float lse = mx + logf(s);
    int b = batch[n];
    atomicAdd(&g_pool[b * H2DIM + sub * 2], v0 - lse);
    atomicAdd(&g_pool[b * H2DIM + sub * 2 + 1], v1 - lse);
    if (sub == 0) atomicAdd(&g_cnt[b], 1.0f);
}

// ---------------- final ----------------
__global__ void final_kernel(const float* __restrict__ lin_W, const float* __restrict__ lin_b,
                             float* __restrict__ out) {
    int g = threadIdx.x;
    if (g >= GG) return;
    float inv = 1.0f / fmaxf(g_cnt[g], 1.0f);
    float acc = lin_b[0];
#pragma unroll
    for (int j = 0; j < H2DIM; j++) acc += g_pool[g * H2DIM + j] * inv * lin_W[j];
    out[g] = acc;
}

// ---------------- launcher ----------------
extern "C" void kernel_launch(void* const* d_in, const int* in_sizes, int n_in,
                              void* d_out, int out_size) {
    const float* x      = (const float*)d_in[0];
    const int*   adj    = (const int*)d_in[1];
    const int*   batch  = (const int*)d_in[2];
    const float* W1     = (const float*)d_in[3];
    const float* a1_src = (const float*)d_in[4];
    const float* a1_dst = (const float*)d_in[5];
    const float* b1     = (const float*)d_in[6];
    const float* W2     = (const float*)d_in[7];
    const float* a2_src = (const float*)d_in[8];
    const float* a2_dst = (const float*)d_in[9];
    const float* b2     = (const float*)d_in[10];
    const float* lin_W  = (const float*)d_in[11];
    const float* lin_b  = (const float*)d_in[12];
    float* out = (float*)d_out;

    const int TB = 256;

    prep_hist_kernel<<<EB + 4, TB>>>(adj, W1, a1_src, a1_dst, W2);
    scan_kernel<<<1, 1024>>>();
    mid_kernel<<<4 * EB, TB>>>(adj, x);   // scatter + gemm1 + alpha1 striped
    agg1_kernel<<<(NN * 32 + TB - 1) / TB, TB>>>(b1);
    gemm2_mma<<<(NN + 127) / 128, TB>>>(a2_src, a2_dst);
    agg2_lsm_kernel<<<(NN * 16 + TB - 1) / TB, TB>>>(b2, batch);
    final_kernel<<<1, 64>>>(lin_W, lin_b, out);
}

// round 11
// speedup vs baseline: 1.9856x; 1.0194x over previous
#include <cuda_runtime.h>
#include <cuda_fp16.h>
#include <math.h>

#define NN 50000
#define EE 800000
#define ET (EE + NN)
#define GG 64
#define F_IN 128
#define H1DIM 256   // HEADS * HID
#define H2DIM 32
#define NEG_SLOPE 0.2f
#define EB 3321                 // ceil(ET/256)
#define G1B 3128                // gemm1 blocks: 782 row-blocks x 4 col-blocks
#define A1B 6250                // alpha1 blocks: NN*32/256

// ---------------- scratch ----------------
__device__ __align__(16) __half g_h1[NN * H1DIM];     // fp16 layer1 features
__device__ __align__(16) __half g_out1h[NN * H1DIM];  // fp16 layer1 output (gemm2 input)
__device__ __align__(16) float g_as1[NN * 4];
__device__ __align__(16) float g_ad1[NN * 4];
__device__ __align__(16) __half g_h2[NN * H2DIM];     // fp16 layer2 features
__device__ float g_as2[NN];
__device__ float g_ad2[NN];
__device__ float g_pool[GG * H2DIM];
__device__ float g_cnt[GG];
__device__ int g_deg[NN];
__device__ int g_cur[NN];
__device__ int g_off[NN + 1];
__device__ int g_csr_src[ET];
__device__ __align__(16) float g_wsd1[F_IN * 8];      // [f][s0..s3,d0..d3]
__device__ __align__(16) __half g_w1h[F_IN * H1DIM];  // fp16 W1
__device__ __align__(16) __half g_w2h[H1DIM * H2DIM]; // fp16 W2

// ---------------- helpers ----------------
__device__ __forceinline__ float leaky(float e) {
    return (e >= 0.f) ? e : NEG_SLOPE * e;
}
__device__ __forceinline__ unsigned smem_u32(const void* p) {
    return (unsigned)__cvta_generic_to_shared(p);
}
__device__ __forceinline__ void ldsm_x4(unsigned& r0, unsigned& r1, unsigned& r2, unsigned& r3, unsigned a) {
    asm volatile("ldmatrix.sync.aligned.m8n8.x4.shared.b16 {%0,%1,%2,%3},[%4];"
                 : "=r"(r0), "=r"(r1), "=r"(r2), "=r"(r3) : "r"(a));
}
__device__ __forceinline__ void ldsm_x4t(unsigned& r0, unsigned& r1, unsigned& r2, unsigned& r3, unsigned a) {
    asm volatile("ldmatrix.sync.aligned.m8n8.x4.trans.shared.b16 {%0,%1,%2,%3},[%4];"
                 : "=r"(r0), "=r"(r1), "=r"(r2), "=r"(r3) : "r"(a));
}
__device__ __forceinline__ void mma16816(float* d, const unsigned* a, unsigned b0, unsigned b1) {
    asm volatile("mma.sync.aligned.m16n8k16.row.col.f32.f16.f16.f32 "
                 "{%0,%1,%2,%3},{%4,%5,%6,%7},{%8,%9},{%0,%1,%2,%3};"
                 : "+f"(d[0]), "+f"(d[1]), "+f"(d[2]), "+f"(d[3])
                 : "r"(a[0]), "r"(a[1]), "r"(a[2]), "r"(a[3]), "r"(b0), "r"(b1));
}

// ---------------- K1: prep (4 blocks) + hist (EB blocks) fused ----------------
__global__ void prep_hist_kernel(const int* __restrict__ adj,
                                 const float* __restrict__ W1,
                                 const float* __restrict__ a1s, const float* __restrict__ a1d,
                                 const float* __restrict__ W2) {
    int bx = blockIdx.x;
    int tid = threadIdx.x;
    if (bx < EB) {
        int e = bx * 256 + tid;
        if (e >= ET) return;
        int dst = (e < EE) ? adj[EE + e] : e - EE;
        atomicAdd(&g_deg[dst], 1);
    } else {
        int pt = (bx - EB) * 256 + tid;  // 0..1023
        {
            int f = pt >> 3, o = pt & 7;
            int h = o & 3, sd = o >> 2;
            const float* a = sd ? a1d : a1s;
            float s = 0.f;
#pragma unroll 8
            for (int d = 0; d < 64; d++) s += W1[f * H1DIM + h * 64 + d] * a[h * 64 + d];
            g_wsd1[f * 8 + o] = s;
        }
        for (int j = pt; j < F_IN * H1DIM; j += 1024) g_w1h[j] = __float2half_rn(W1[j]);
        for (int j = pt; j < H1DIM * H2DIM; j += 1024) g_w2h[j] = __float2half_rn(W2[j]);
        for (int j = pt; j < GG * H2DIM; j += 1024) g_pool[j] = 0.f;
        if (pt < GG) g_cnt[pt] = 0.f;
    }
}

// ---------------- K2: coalesced block scan ----------------
__global__ void scan_kernel() {
    __shared__ int warpsum[32];
    int tid = threadIdx.x;
    int lane = tid & 31, wid = tid >> 5;
    int running = 0;
    for (int base = 0; base < NN; base += 1024) {
        int i = base + tid;
        int v = (i < NN) ? g_deg[i] : 0;
        int val = v;
#pragma unroll
        for (int off = 1; off < 32; off <<= 1) {
            int t = __shfl_up_sync(0xffffffffu, val, off);
            if (lane >= off) val += t;
        }
        if (lane == 31) warpsum[wid] = val;
        __syncthreads();
        if (wid == 0) {
            int s = warpsum[lane];
#pragma unroll
            for (int off = 1; off < 32; off <<= 1) {
                int t = __shfl_up_sync(0xffffffffu, s, off);
                if (lane >= off) s += t;
            }
            warpsum[lane] = s;
        }
        __syncthreads();
        int warpbase = (wid == 0) ? 0 : warpsum[wid - 1];
        int excl = running + warpbase + val - v;
        if (i < NN) { g_off[i] = excl; g_cur[i] = excl; }
        running += warpsum[31];
        __syncthreads();
    }
    if (tid == 0) g_off[NN] = running;
}

// ---------------- K3 bodies ----------------
__device__ __forceinline__ void scatter_body(int base, const int* __restrict__ adj) {
    int tid = threadIdx.x;
    int gt = base * 256 + tid;
    const int STR = EB * 256;
    for (int j = gt; j < NN; j += STR) g_deg[j] = 0;   // reset for next replay
    if (gt >= ET) return;
    int src, dst;
    if (gt < EE) { src = adj[gt]; dst = adj[EE + gt]; }
    else         { src = dst = gt - EE; }
    int p = atomicAdd(&g_cur[dst], 1);
    g_csr_src[p] = src;
}

__device__ __forceinline__ void alpha1_body(int aid, const float* __restrict__ x) {
    int gt = aid * 256 + threadIdx.x;
    int n = gt >> 5, lane = gt & 31;
    if (n >= NN) return;
    float4 xv = ((const float4*)x)[n * 32 + lane];
    float a0 = 0, a1 = 0, a2 = 0, a3 = 0, b0 = 0, b1 = 0, b2 = 0, b3 = 0;
    float xj[4] = {xv.x, xv.y, xv.z, xv.w};
#pragma unroll
    for (int j = 0; j < 4; j++) {
        int f = lane * 4 + j;
        float4 wa = *(const float4*)&g_wsd1[f * 8];
        float4 wb = *(const float4*)&g_wsd1[f * 8 + 4];
        a0 = fmaf(xj[j], wa.x, a0); a1 = fmaf(xj[j], wa.y, a1);
        a2 = fmaf(xj[j], wa.z, a2); a3 = fmaf(xj[j], wa.w, a3);
        b0 = fmaf(xj[j], wb.x, b0); b1 = fmaf(xj[j], wb.y, b1);
        b2 = fmaf(xj[j], wb.z, b2); b3 = fmaf(xj[j], wb.w, b3);
    }
#pragma unroll
    for (int off = 16; off; off >>= 1) {
        a0 += __shfl_xor_sync(0xffffffffu, a0, off);
        a1 += __shfl_xor_sync(0xffffffffu, a1, off);
        a2 += __shfl_xor_sync(0xffffffffu, a2, off);
        a3 += __shfl_xor_sync(0xffffffffu, a3, off);
        b0 += __shfl_xor_sync(0xffffffffu, b0, off);
        b1 += __shfl_xor_sync(0xffffffffu, b1, off);
        b2 += __shfl_xor_sync(0xffffffffu, b2, off);
        b3 += __shfl_xor_sync(0xffffffffu, b3, off);
    }
    if (lane == 0) {
        *(float4*)&g_as1[n * 4] = make_float4(a0, a1, a2, a3);
        *(float4*)&g_ad1[n * 4] = make_float4(b0, b1, b2, b3);
    }
}

// ---------------- K3: scatter + gemm1(HMMA) + alpha1, striped roles ----------------
__global__ __launch_bounds__(256) void mid_kernel(const int* __restrict__ adj,
                                                  const float* __restrict__ x) {
    __shared__ __align__(16) __half As[64][136];
    __shared__ __align__(16) __half Bs[128][72];
    int m = blockIdx.x & 3, base = blockIdx.x >> 2;
    if (m == 2) { if (base < EB) scatter_body(base, adj); return; }
    if (m & 1)  { int aid = base * 2 + (m == 3); if (aid < A1B) alpha1_body(aid, x); return; }
    if (base >= G1B) return;
    int tid = threadIdx.x;
    int row0 = (base >> 2) * 64;
    int col0 = (base & 3) * 64;
    for (int i = tid; i < 64 * 32; i += 256) {
        int r = i >> 5, c4 = i & 31;
        int row = row0 + r;
        float4 v = (row < NN) ? *(const float4*)&x[row * F_IN + c4 * 4]
                              : make_float4(0.f, 0.f, 0.f, 0.f);
        *(half2*)&As[r][c4 * 4] = __floats2half2_rn(v.x, v.y);
        *(half2*)&As[r][c4 * 4 + 2] = __floats2half2_rn(v.z, v.w);
    }
    for (int i = tid; i < 128 * 8; i += 256) {
        int r = i >> 3, c8 = i & 7;
        *(uint4*)&Bs[r][c8 * 8] = *(const uint4*)&g_w1h[r * H1DIM + col0 + c8 * 8];
    }
    __syncthreads();
    int wid = tid >> 5, lane = tid & 31;
    int rowg = wid >> 1, colg = wid & 1;
    unsigned a[8][4];
#pragma unroll
    for (int ks = 0; ks < 8; ks++) {
        unsigned addr = smem_u32(&As[rowg * 16 + (lane & 15)][ks * 16 + (lane >> 4) * 8]);
        ldsm_x4(a[ks][0], a[ks][1], a[ks][2], a[ks][3], addr);
    }
    float d[4][4];
#pragma unroll
    for (int nt = 0; nt < 4; nt++)
#pragma unroll
        for (int j = 0; j < 4; j++) d[nt][j] = 0.f;
#pragma unroll
    for (int np = 0; np < 2; np++) {
#pragma unroll
        for (int ks = 0; ks < 8; ks++) {
            unsigned b0, b1, b2, b3;
            unsigned addr = smem_u32(&Bs[ks * 16 + (lane & 15)][colg * 32 + np * 16 + (lane >> 4) * 8]);
            ldsm_x4t(b0, b1, b2, b3, addr);
            mma16816(d[np * 2], a[ks], b0, b1);
            mma16816(d[np * 2 + 1], a[ks], b2, b3);
        }
    }
    int g = lane >> 2, t = lane & 3;
    int r_lo = row0 + rowg * 16 + g;
    int r_hi = r_lo + 8;
#pragma unroll
    for (int nt = 0; nt < 4; nt++) {
        int col = col0 + colg * 32 + nt * 8 + 2 * t;
        if (r_lo < NN) *(half2*)&g_h1[r_lo * H1DIM + col] = __floats2half2_rn(d[nt][0], d[nt][1]);
        if (r_hi < NN) *(half2*)&g_h1[r_hi * H1DIM + col] = __floats2half2_rn(d[nt][2], d[nt][3]);
    }
}

// ---------------- agg1: 32 threads/node, shuffle-split exp, HFMA2 accumulation ----------------
__global__ void agg1_kernel(const float* __restrict__ b1) {
    int gt = blockIdx.x * blockDim.x + threadIdx.x;
    int n = gt >> 5;
    if (n >= NN) return;
    int c = gt & 31;
    int head = c >> 3;
    int q = c & 3;                       // lane's slot in the unroll-4 group
    float4 adv = *(const float4*)&g_ad1[n * 4];
    float ad_all[4] = {adv.x, adv.y, adv.z, adv.w};
    float adh = ad_all[head];
    int beg = g_off[n], end = g_off[n + 1];
    half2 acc[4];
#pragma unroll
    for (int j = 0; j < 4; j++) acc[j] = __floats2half2_rn(0.f, 0.f);
    float den = 0.f;
    int i = beg;
    for (; i + 4 <= end; i += 4) {
        // each quarter-lane computes e for ONE edge (its own head), then broadcast within head-octet
        int sq = g_csr_src[i + q];
        float eq = __expf(leaky(g_as1[sq * 4 + head] + adh));
        float e0 = __shfl_sync(0xffffffffu, eq, (c & 24) + 0);
        float e1 = __shfl_sync(0xffffffffu, eq, (c & 24) + 1);
        float e2 = __shfl_sync(0xffffffffu, eq, (c & 24) + 2);
        float e3 = __shfl_sync(0xffffffffu, eq, (c & 24) + 3);
        int s0 = g_csr_src[i], s1 = g_csr_src[i + 1];
        int s2 = g_csr_src[i + 2], s3 = g_csr_src[i + 3];
        uint4 p0 = ((const uint4*)(g_h1 + s0 * H1DIM))[c];
        uint4 p1 = ((const uint4*)(g_h1 + s1 * H1DIM))[c];
        uint4 p2 = ((const uint4*)(g_h1 + s2 * H1DIM))[c];
        uint4 p3 = ((const uint4*)(g_h1 + s3 * H1DIM))[c];
        den += (e0 + e1) + (e2 + e3);
        half2 h0 = __float2half2_rn(e0), h1e = __float2half2_rn(e1);
        half2 h2e = __float2half2_rn(e2), h3e = __float2half2_rn(e3);
        acc[0] = __hfma2(h0, *(const half2*)&p0.x, acc[0]);
        acc[1] = __hfma2(h0, *(const half2*)&p0.y, acc[1]);
        acc[2] = __hfma2(h0, *(const half2*)&p0.z, acc[2]);
        acc[3] = __hfma2(h0, *(const half2*)&p0.w, acc[3]);
        acc[0] = __hfma2(h1e, *(const half2*)&p1.x, acc[0]);
        acc[1] = __hfma2(h1e, *(const half2*)&p1.y, acc[1]);
        acc[2] = __hfma2(h1e, *(const half2*)&p1.z, acc[2]);
        acc[3] = __hfma2(h1e, *(const half2*)&p1.w, acc[3]);
        acc[0] = __hfma2(h2e, *(const half2*)&p2.x, acc[0]);
        acc[1] = __hfma2(h2e, *(const half2*)&p2.y, acc[1]);
        acc[2] = __hfma2(h2e, *(const half2*)&p2.z, acc[2]);
        acc[3] = __hfma2(h2e, *(const half2*)&p2.w, acc[3]);
        acc[0] = __hfma2(h3e, *(const half2*)&p3.x, acc[0]);
        acc[1] = __hfma2(h3e, *(const half2*)&p3.y, acc[1]);
        acc[2] = __hfma2(h3e, *(const half2*)&p3.z, acc[2]);
        acc[3] = __hfma2(h3e, *(const half2*)&p3.w, acc[3]);
    }
    for (; i < end; i++) {
        int s0 = g_csr_src[i];
        float e0 = __expf(leaky(g_as1[s0 * 4 + head] + adh));
        uint4 p0 = ((const uint4*)(g_h1 + s0 * H1DIM))[c];
        den += e0;
        half2 h0 = __float2half2_rn(e0);
        acc[0] = __hfma2(h0, *(const half2*)&p0.x, acc[0]);
        acc[1] = __hfma2(h0, *(const half2*)&p0.y, acc[1]);
        acc[2] = __hfma2(h0, *(const half2*)&p0.z, acc[2]);
        acc[3] = __hfma2(h0, *(const half2*)&p0.w, acc[3]);
    }
    float inv = __fdividef(1.0f, den);
    float4 ba = ((const float4*)b1)[c * 2];
    float4 bb = ((const float4*)b1)[c * 2 + 1];
    float2 f0 = __half22float2(acc[0]);
    float2 f1 = __half22float2(acc[1]);
    float2 f2 = __half22float2(acc[2]);
    float2 f3 = __half22float2(acc[3]);
    half2 o0 = __floats2half2_rn(fmaxf(fmaf(f0.x, inv, ba.x), 0.f), fmaxf(fmaf(f0.y, inv, ba.y), 0.f));
    half2 o1 = __floats2half2_rn(fmaxf(fmaf(f1.x, inv, ba.z), 0.f), fmaxf(fmaf(f1.y, inv, ba.w), 0.f));
    half2 o2 = __floats2half2_rn(fmaxf(fmaf(f2.x, inv, bb.x), 0.f), fmaxf(fmaf(f2.y, inv, bb.y), 0.f));
    half2 o3 = __floats2half2_rn(fmaxf(fmaf(f3.x, inv, bb.z), 0.f), fmaxf(fmaf(f3.y, inv, bb.w), 0.f));
    uint4 pk;
    pk.x = *(unsigned*)&o0; pk.y = *(unsigned*)&o1; pk.z = *(unsigned*)&o2; pk.w = *(unsigned*)&o3;
    ((uint4*)(g_out1h + n * H1DIM))[c] = pk;
}

// ---------------- GEMM2 (HMMA) + alpha2 ----------------
__global__ __launch_bounds__(256) void gemm2_mma(const float* __restrict__ a2s,
                                                 const float* __restrict__ a2d) {
    __shared__ __align__(16) __half As[128][136];
    __shared__ __align__(16) __half Bs[128][40];
    int tid = threadIdx.x;
    int row0 = blockIdx.x * 128;
    int wid = tid >> 5, lane = tid & 31;
    float d[4][4];
#pragma unroll
    for (int nt = 0; nt < 4; nt++)
#pragma unroll
        for (int j = 0; j < 4; j++) d[nt][j] = 0.f;
    for (int st = 0; st < 2; st++) {
        for (int i = tid; i < 128 * 16; i += 256) {
            int r = i >> 4, c8 = i & 15;
            int row = row0 + r;
            uint4 v = (row < NN) ? *(const uint4*)&g_out1h[row * H1DIM + st * 128 + c8 * 8]
                                 : make_uint4(0u, 0u, 0u, 0u);
            *(uint4*)&As[r][c8 * 8] = v;
        }
        for (int i = tid; i < 128 * 4; i += 256) {
            int r = i >> 2, c8 = i & 3;
            *(uint4*)&Bs[r][c8 * 8] = *(const uint4*)&g_w2h[(st * 128 + r) * H2DIM + c8 * 8];
        }
        __syncthreads();
#pragma unroll
        for (int ks = 0; ks < 8; ks++) {
            unsigned a[4];
            unsigned aaddr = smem_u32(&As[wid * 16 + (lane & 15)][ks * 16 + (lane >> 4) * 8]);
            ldsm_x4(a[0], a[1], a[2], a[3], aaddr);
#pragma unroll
            for (int np = 0; np < 2; np++) {
                unsigned b0, b1, b2, b3;
                unsigned baddr = smem_u32(&Bs[ks * 16 + (lane & 15)][np * 16 + (lane >> 4) * 8]);
                ldsm_x4t(b0, b1, b2, b3, baddr);
                mma16816(d[np * 2], a, b0, b1);
                mma16816(d[np * 2 + 1], a, b2, b3);
            }
        }
        __syncthreads();
    }
    int g = lane >> 2, t = lane & 3;
    int r_lo = row0 + wid * 16 + g;
    int r_hi = r_lo + 8;
    float ps_lo = 0, pd_lo = 0, ps_hi = 0, pd_hi = 0;
#pragma unroll
    for (int nt = 0; nt < 4; nt++) {
        int col = nt * 8 + 2 * t;
        float s0 = a2s[col], s1 = a2s[col + 1];
        float t0 = a2d[col], t1 = a2d[col + 1];
        if (r_lo < NN) *(half2*)&g_h2[r_lo * H2DIM + col] = __floats2half2_rn(d[nt][0], d[nt][1]);
        if (r_hi < NN) *(half2*)&g_h2[r_hi * H2DIM + col] = __floats2half2_rn(d[nt][2], d[nt][3]);
        ps_lo += d[nt][0] * s0 + d[nt][1] * s1;
        pd_lo += d[nt][0] * t0 + d[nt][1] * t1;
        ps_hi += d[nt][2] * s0 + d[nt][3] * s1;
        pd_hi += d[nt][2] * t0 + d[nt][3] * t1;
    }
#pragma unroll
    for (int off = 1; off <= 2; off <<= 1) {
        ps_lo += __shfl_xor_sync(0xffffffffu, ps_lo, off);
        pd_lo += __shfl_xor_sync(0xffffffffu, pd_lo, off);
        ps_hi += __shfl_xor_sync(0xffffffffu, ps_hi, off);
        pd_hi += __shfl_xor_sync(0xffffffffu, pd_hi, off);
    }
    if (t == 0) {
        if (r_lo < NN) { g_as2[r_lo] = ps_lo; g_ad2[r_lo] = pd_lo; }
        if (r_hi < NN) { g_as2[r_hi] = ps_hi; g_ad2[r_hi] = pd_hi; }
    }
}

// ---------------- agg2 + bias + log_softmax + pool ----------------
__global__ void agg2_lsm_kernel(const float* __restrict__ b2, const int* __restrict__ batch) {
    int gt = blockIdx.x * blockDim.x + threadIdx.x;
    int n = gt >> 4;
    if (n >= NN) return;
    int sub = gt & 15;
    float ad = g_ad2[n];
    int beg = g_off[n], end = g_off[n + 1];
    half2 acc = __floats2half2_rn(0.f, 0.f);
    float den = 0.f;
    int i = beg;
    for (; i + 2 <= end; i += 2) {
        int s0 = g_csr_src[i], s1 = g_csr_src[i + 1];
        float e0 = __expf(leaky(g_as2[s0] + ad));
        float e1 = __expf(leaky(g_as2[s1] + ad));
        half2 f0 = ((const half2*)(g_h2 + s0 * H2DIM))[sub];
        half2 f1 = ((const half2*)(g_h2 + s1 * H2DIM))[sub];
        den += e0 + e1;
        acc = __hfma2(__float2half2_rn(e0), f0, acc);
        acc = __hfma2(__float2half2_rn(e1), f1, acc);
    }
    if (i < end) {
        int s0 = g_csr_src[i];
        float e0 = __expf(leaky(g_as2[s0] + ad));
        half2 f0 = ((const half2*)(g_h2 + s0 * H2DIM))[sub];
        den += e0;
        acc = __hfma2(__float2half2_rn(e0), f0, acc);
    }
    float2 fa = __half22float2(acc);
    float inv = __fdividef(1.0f, den);
    float v0 = fmaf(fa.x, inv, b2[sub * 2]);
    float v1 = fmaf(fa.y, inv, b2[sub * 2 + 1]);
    float mx = fmaxf(v0, v1);
#pragma unroll
    for (int off = 8; off; off >>= 1) mx = fmaxf(mx, __shfl_xor_sync(0xffffffffu, mx, off));
    float s = expf(v0 - mx) + expf(v1 - mx);
#pragma unroll
    for (int off = 8; off; off >>= 1) s += __shfl_xor_sync(0xffffffffu, s, off);
    float lse = mx + logf(s);
    int b = batch[n];
    atomicAdd(&g_pool[b * H2DIM + sub * 2], v0 - lse);
    atomicAdd(&g_pool[b * H2DIM + sub * 2 + 1], v1 - lse);
    if (sub == 0) atomicAdd(&g_cnt[b], 1.0f);
}

// ---------------- final ----------------
__global__ void final_kernel(const float* __restrict__ lin_W, const float* __restrict__ lin_b,
                             float* __restrict__ out) {
    int g = threadIdx.x;
    if (g >= GG) return;
    float inv = 1.0f / fmaxf(g_cnt[g], 1.0f);
    float acc = lin_b[0];
#pragma unroll
    for (int j = 0; j < H2DIM; j++) acc += g_pool[g * H2DIM + j] * inv * lin_W[j];
    out[g] = acc;
}

// ---------------- launcher ----------------
extern "C" void kernel_launch(void* const* d_in, const int* in_sizes, int n_in,
                              void* d_out, int out_size) {
    const float* x      = (const float*)d_in[0];
    const int*   adj    = (const int*)d_in[1];
    const int*   batch  = (const int*)d_in[2];
    const float* W1     = (const float*)d_in[3];
    const float* a1_src = (const float*)d_in[4];
    const float* a1_dst = (const float*)d_in[5];
    const float* b1     = (const float*)d_in[6];
    const float* W2     = (const float*)d_in[7];
    const float* a2_src = (const float*)d_in[8];
    const float* a2_dst = (const float*)d_in[9];
    const float* b2     = (const float*)d_in[10];
    const float* lin_W  = (const float*)d_in[11];
    const float* lin_b  = (const float*)d_in[12];
    float* out = (float*)d_out;

    const int TB = 256;

    prep_hist_kernel<<<EB + 4, TB>>>(adj, W1, a1_src, a1_dst, W2);
    scan_kernel<<<1, 1024>>>();
    mid_kernel<<<4 * EB, TB>>>(adj, x);   // scatter + gemm1 + alpha1 striped
    agg1_kernel<<<(NN * 32 + TB - 1) / TB, TB>>>(b1);
    gemm2_mma<<<(NN + 127) / 128, TB>>>(a2_src, a2_dst);
    agg2_lsm_kernel<<<(NN * 16 + TB - 1) / TB, TB>>>(b2, batch);
    final_kernel<<<1, 64>>>(lin_W, lin_b, out);
}